// round 1
// baseline (speedup 1.0000x reference)
#include <cuda_runtime.h>
#include <math.h>
#include <stdint.h>

// ---------------------------------------------------------------------------
// MultiHeadAttention: x@Wq/Wk/Wv -> causal flash attention -> @Wo
// B=4, S=2048, E=1024, H=16, Hs=64. All fp32 I/O, TF32 tensor-core math.
// ---------------------------------------------------------------------------

#define BATCH 4
#define SEQ   2048
#define EMBD  1024
#define NHEAD 16
#define HDIM  64
#define MROWS (BATCH*SEQ)   // 8192

// Scratch (device globals; no runtime allocation allowed)
__device__ float g_Q[MROWS * EMBD];
__device__ float g_K[MROWS * EMBD];
__device__ float g_V[MROWS * EMBD];
__device__ float g_A[MROWS * EMBD];

__device__ __forceinline__ unsigned f2tf(float x) {
    unsigned u;
    asm("cvt.rna.tf32.f32 %0, %1;" : "=r"(u) : "f"(x));
    return u;
}

__device__ __forceinline__ void mma8(float* c, const unsigned* a, const unsigned* b) {
    asm volatile(
        "mma.sync.aligned.m16n8k8.row.col.f32.tf32.tf32.f32 "
        "{%0,%1,%2,%3}, {%4,%5,%6,%7}, {%8,%9}, {%0,%1,%2,%3};\n"
        : "+f"(c[0]), "+f"(c[1]), "+f"(c[2]), "+f"(c[3])
        : "r"(a[0]), "r"(a[1]), "r"(a[2]), "r"(a[3]),
          "r"(b[0]), "r"(b[1]));
}

// ---------------------------------------------------------------------------
// TF32 GEMM: C[M,N] = A[M,K] @ B[K,N], row-major. CTA tile 128x128x32.
// 256 threads = 8 warps (4m x 2n), warp tile 32x64 (2 m-frags x 8 n-frags).
// ---------------------------------------------------------------------------
#define BM 128
#define BN 128
#define BK 32
#define AS_STRIDE 36    // pad: banks = l4*4 + lm4 (conflict-free)
#define BS_STRIDE 136   // pad: banks = lm4*8 + l4 (conflict-free)

__global__ __launch_bounds__(256) void gemm_tf32(
    const float* __restrict__ A, const float* __restrict__ B,
    float* __restrict__ C, int M, int N, int K)
{
    __shared__ unsigned As[BM * AS_STRIDE];
    __shared__ unsigned Bs[BK * BS_STRIDE];

    const int tid  = threadIdx.x;
    const int warp = tid >> 5;
    const int lane = tid & 31;
    const int l4   = lane >> 2;
    const int lm4  = lane & 3;
    const int wm0  = (warp >> 1) * 32;
    const int wn0  = (warp & 1) * 64;
    const int m0   = blockIdx.y * BM;
    const int n0   = blockIdx.x * BN;

    float acc[2][8][4];
    #pragma unroll
    for (int mi = 0; mi < 2; mi++)
        #pragma unroll
        for (int ni = 0; ni < 8; ni++)
            #pragma unroll
            for (int q = 0; q < 4; q++)
                acc[mi][ni][q] = 0.0f;

    for (int k0 = 0; k0 < K; k0 += BK) {
        // Load A tile 128x32 (1024 float4, 4 per thread), convert to tf32
        #pragma unroll
        for (int t = 0; t < 4; t++) {
            int idx = tid + t * 256;
            int r = idx >> 3;
            int c = (idx & 7) * 4;
            float4 v = *(const float4*)(A + (size_t)(m0 + r) * K + k0 + c);
            uint4 u = make_uint4(f2tf(v.x), f2tf(v.y), f2tf(v.z), f2tf(v.w));
            *(uint4*)&As[r * AS_STRIDE + c] = u;
        }
        // Load B tile 32x128
        #pragma unroll
        for (int t = 0; t < 4; t++) {
            int idx = tid + t * 256;
            int r = idx >> 5;
            int c = (idx & 31) * 4;
            float4 v = *(const float4*)(B + (size_t)(k0 + r) * N + n0 + c);
            uint4 u = make_uint4(f2tf(v.x), f2tf(v.y), f2tf(v.z), f2tf(v.w));
            *(uint4*)&Bs[r * BS_STRIDE + c] = u;
        }
        __syncthreads();

        #pragma unroll
        for (int kk = 0; kk < BK; kk += 8) {
            unsigned a[2][4];
            #pragma unroll
            for (int mi = 0; mi < 2; mi++) {
                int rb = wm0 + mi * 16;
                a[mi][0] = As[(rb + l4)     * AS_STRIDE + kk + lm4];
                a[mi][1] = As[(rb + l4 + 8) * AS_STRIDE + kk + lm4];
                a[mi][2] = As[(rb + l4)     * AS_STRIDE + kk + lm4 + 4];
                a[mi][3] = As[(rb + l4 + 8) * AS_STRIDE + kk + lm4 + 4];
            }
            #pragma unroll
            for (int ni = 0; ni < 8; ni++) {
                unsigned b[2];
                int cb = wn0 + ni * 8;
                b[0] = Bs[(kk + lm4)     * BS_STRIDE + cb + l4];
                b[1] = Bs[(kk + lm4 + 4) * BS_STRIDE + cb + l4];
                mma8(acc[0][ni], a[0], b);
                mma8(acc[1][ni], a[1], b);
            }
        }
        __syncthreads();
    }

    // Epilogue
    #pragma unroll
    for (int mi = 0; mi < 2; mi++) {
        #pragma unroll
        for (int ni = 0; ni < 8; ni++) {
            int row = m0 + wm0 + mi * 16 + l4;
            int col = n0 + wn0 + ni * 8 + lm4 * 2;
            *(float2*)&C[(size_t)row * N + col] =
                make_float2(acc[mi][ni][0], acc[mi][ni][1]);
            *(float2*)&C[(size_t)(row + 8) * N + col] =
                make_float2(acc[mi][ni][2], acc[mi][ni][3]);
        }
    }
}

// ---------------------------------------------------------------------------
// Causal flash attention (TF32 mma), one CTA = 64 q-rows of one (b,h).
// 128 threads = 4 warps; warp w owns q-rows [w*16, w*16+16).
// ---------------------------------------------------------------------------
#define QST 68   // Q smem stride (uints)
#define KST 68
#define VST 72
#define PST 68
#define ATTN_SMEM ((64*QST + 64*KST + 64*VST + 64*PST) * 4)  // 70656 bytes

__global__ __launch_bounds__(128) void attn_flash(
    const float* __restrict__ Q, const float* __restrict__ K,
    const float* __restrict__ V, float* __restrict__ O)
{
    extern __shared__ unsigned smemA[];
    unsigned* Qs = smemA;
    unsigned* Ks = Qs + 64 * QST;
    unsigned* Vs = Ks + 64 * KST;
    unsigned* Ps = Vs + 64 * VST;

    const int tid  = threadIdx.x;
    const int warp = tid >> 5;
    const int lane = tid & 31;
    const int l4   = lane >> 2;
    const int lm4  = lane & 3;
    const int w16  = warp * 16;

    const int qi = blockIdx.x;          // q tile (0..31)
    const int bh = blockIdx.y;          // 0..63
    const int b  = bh >> 4;
    const int h  = bh & 15;
    const size_t headoff = (size_t)b * SEQ * EMBD + (size_t)h * HDIM;
    const float SCALE = 0.125f;         // 1/sqrt(64)

    // Load Q tile (64 rows x 64 dims), convert to tf32
    #pragma unroll
    for (int t = 0; t < 8; t++) {
        int idx = tid + t * 128;
        int r = idx >> 4;
        int c = (idx & 15) * 4;
        float4 v = *(const float4*)(Q + headoff + (size_t)(qi * 64 + r) * EMBD + c);
        *(uint4*)&Qs[r * QST + c] = make_uint4(f2tf(v.x), f2tf(v.y), f2tf(v.z), f2tf(v.w));
    }

    float m0 = -INFINITY, m1 = -INFINITY, l0 = 0.0f, l1 = 0.0f;
    float o[8][4];
    #pragma unroll
    for (int ni = 0; ni < 8; ni++)
        #pragma unroll
        for (int q = 0; q < 4; q++) o[ni][q] = 0.0f;

    for (int j = 0; j <= qi; j++) {
        __syncthreads();
        // Load K_j, V_j tiles
        #pragma unroll
        for (int t = 0; t < 8; t++) {
            int idx = tid + t * 128;
            int r = idx >> 4;
            int c = (idx & 15) * 4;
            float4 vk = *(const float4*)(K + headoff + (size_t)(j * 64 + r) * EMBD + c);
            *(uint4*)&Ks[r * KST + c] = make_uint4(f2tf(vk.x), f2tf(vk.y), f2tf(vk.z), f2tf(vk.w));
            float4 vv = *(const float4*)(V + headoff + (size_t)(j * 64 + r) * EMBD + c);
            *(uint4*)&Vs[r * VST + c] = make_uint4(f2tf(vv.x), f2tf(vv.y), f2tf(vv.z), f2tf(vv.w));
        }
        __syncthreads();

        // S = Q K^T (warp: 16 rows x 64 key-cols)
        float s[8][4];
        #pragma unroll
        for (int ni = 0; ni < 8; ni++)
            #pragma unroll
            for (int q = 0; q < 4; q++) s[ni][q] = 0.0f;

        #pragma unroll
        for (int kk = 0; kk < 64; kk += 8) {
            unsigned a[4];
            a[0] = Qs[(w16 + l4)     * QST + kk + lm4];
            a[1] = Qs[(w16 + l4 + 8) * QST + kk + lm4];
            a[2] = Qs[(w16 + l4)     * QST + kk + lm4 + 4];
            a[3] = Qs[(w16 + l4 + 8) * QST + kk + lm4 + 4];
            #pragma unroll
            for (int ni = 0; ni < 8; ni++) {
                unsigned bfr[2];
                bfr[0] = Ks[(ni * 8 + l4) * KST + kk + lm4];
                bfr[1] = Ks[(ni * 8 + l4) * KST + kk + lm4 + 4];
                mma8(s[ni], a, bfr);
            }
        }

        // Scale + causal mask + row max
        const bool diag = (j == qi);
        const int grow0 = qi * 64 + w16 + l4;
        const int grow1 = grow0 + 8;
        float rm0 = -INFINITY, rm1 = -INFINITY;
        #pragma unroll
        for (int ni = 0; ni < 8; ni++) {
            int gc = j * 64 + ni * 8 + lm4 * 2;
            float v0 = s[ni][0] * SCALE;
            float v1 = s[ni][1] * SCALE;
            float v2 = s[ni][2] * SCALE;
            float v3 = s[ni][3] * SCALE;
            if (diag) {
                if (gc     > grow0) v0 = -INFINITY;
                if (gc + 1 > grow0) v1 = -INFINITY;
                if (gc     > grow1) v2 = -INFINITY;
                if (gc + 1 > grow1) v3 = -INFINITY;
            }
            s[ni][0] = v0; s[ni][1] = v1; s[ni][2] = v2; s[ni][3] = v3;
            rm0 = fmaxf(rm0, fmaxf(v0, v1));
            rm1 = fmaxf(rm1, fmaxf(v2, v3));
        }
        #pragma unroll
        for (int off = 1; off < 4; off <<= 1) {
            rm0 = fmaxf(rm0, __shfl_xor_sync(0xffffffffu, rm0, off));
            rm1 = fmaxf(rm1, __shfl_xor_sync(0xffffffffu, rm1, off));
        }

        float nm0 = fmaxf(m0, rm0);
        float nm1 = fmaxf(m1, rm1);
        float a0 = __expf(m0 - nm0);
        float a1 = __expf(m1 - nm1);
        m0 = nm0; m1 = nm1;

        float rs0 = 0.0f, rs1 = 0.0f;
        #pragma unroll
        for (int ni = 0; ni < 8; ni++) {
            float p0 = __expf(s[ni][0] - nm0);
            float p1 = __expf(s[ni][1] - nm0);
            float p2 = __expf(s[ni][2] - nm1);
            float p3 = __expf(s[ni][3] - nm1);
            rs0 += p0 + p1;
            rs1 += p2 + p3;
            int col = ni * 8 + lm4 * 2;
            Ps[(w16 + l4)     * PST + col]     = f2tf(p0);
            Ps[(w16 + l4)     * PST + col + 1] = f2tf(p1);
            Ps[(w16 + l4 + 8) * PST + col]     = f2tf(p2);
            Ps[(w16 + l4 + 8) * PST + col + 1] = f2tf(p3);
            o[ni][0] *= a0; o[ni][1] *= a0;
            o[ni][2] *= a1; o[ni][3] *= a1;
        }
        #pragma unroll
        for (int off = 1; off < 4; off <<= 1) {
            rs0 += __shfl_xor_sync(0xffffffffu, rs0, off);
            rs1 += __shfl_xor_sync(0xffffffffu, rs1, off);
        }
        l0 = a0 * l0 + rs0;
        l1 = a1 * l1 + rs1;

        __syncwarp();

        // O += P @ V (k dim = 64 keys)
        #pragma unroll
        for (int kk = 0; kk < 64; kk += 8) {
            unsigned a[4];
            a[0] = Ps[(w16 + l4)     * PST + kk + lm4];
            a[1] = Ps[(w16 + l4 + 8) * PST + kk + lm4];
            a[2] = Ps[(w16 + l4)     * PST + kk + lm4 + 4];
            a[3] = Ps[(w16 + l4 + 8) * PST + kk + lm4 + 4];
            #pragma unroll
            for (int ni = 0; ni < 8; ni++) {
                unsigned bfr[2];
                bfr[0] = Vs[(kk + lm4)     * VST + ni * 8 + l4];
                bfr[1] = Vs[(kk + lm4 + 4) * VST + ni * 8 + l4];
                mma8(o[ni], a, bfr);
            }
        }
    }

    // Epilogue: normalize and store to [B*S, EMBD] at head offset
    float i0 = 1.0f / l0;
    float i1 = 1.0f / l1;
    #pragma unroll
    for (int ni = 0; ni < 8; ni++) {
        int gr = b * SEQ + qi * 64 + w16 + l4;
        int gc = h * HDIM + ni * 8 + lm4 * 2;
        *(float2*)&O[(size_t)gr * EMBD + gc] =
            make_float2(o[ni][0] * i0, o[ni][1] * i0);
        *(float2*)&O[(size_t)(gr + 8) * EMBD + gc] =
            make_float2(o[ni][2] * i1, o[ni][3] * i1);
    }
}

// ---------------------------------------------------------------------------
// Launch
// ---------------------------------------------------------------------------
extern "C" void kernel_launch(void* const* d_in, const int* in_sizes, int n_in,
                              void* d_out, int out_size)
{
    const float* x  = (const float*)d_in[0];
    const float* Wq = (const float*)d_in[1];
    const float* Wk = (const float*)d_in[2];
    const float* Wv = (const float*)d_in[3];
    const float* Wo = (const float*)d_in[4];
    float* out = (float*)d_out;

    float *Qp, *Kp, *Vp, *Ap;
    cudaGetSymbolAddress((void**)&Qp, g_Q);
    cudaGetSymbolAddress((void**)&Kp, g_K);
    cudaGetSymbolAddress((void**)&Vp, g_V);
    cudaGetSymbolAddress((void**)&Ap, g_A);

    cudaFuncSetAttribute(attn_flash,
                         cudaFuncAttributeMaxDynamicSharedMemorySize, ATTN_SMEM);

    dim3 gg(EMBD / BN, MROWS / BM);   // (8, 64)
    gemm_tf32<<<gg, 256>>>(x, Wq, Qp, MROWS, EMBD, EMBD);
    gemm_tf32<<<gg, 256>>>(x, Wk, Kp, MROWS, EMBD, EMBD);
    gemm_tf32<<<gg, 256>>>(x, Wv, Vp, MROWS, EMBD, EMBD);

    dim3 ga(SEQ / 64, BATCH * NHEAD); // (32, 64)
    attn_flash<<<ga, 128, ATTN_SMEM>>>(Qp, Kp, Vp, Ap);

    gemm_tf32<<<gg, 256>>>(Ap, Wo, out, MROWS, EMBD, EMBD);
}

// round 2
// speedup vs baseline: 1.0815x; 1.0815x over previous
#include <cuda_runtime.h>
#include <math.h>
#include <stdint.h>

// ---------------------------------------------------------------------------
// MultiHeadAttention: x@Wq/Wk/Wv -> causal flash attention -> @Wo
// B=4, S=2048, E=1024, H=16, Hs=64. fp32 I/O, TF32 tensor-core math.
// R2: pre-rounded tf32 inputs + cp.async double-buffered GEMM + fused QKV
//     + 128-row attention tiles with 2 CTAs/SM and longest-first scheduling.
// ---------------------------------------------------------------------------

#define BATCH 4
#define SEQ   2048
#define EMBD  1024
#define NHEAD 16
#define HDIM  64
#define MROWS (BATCH*SEQ)   // 8192

// Scratch (device globals; no runtime allocation allowed)
__device__ float g_Q[MROWS * EMBD];
__device__ float g_K[MROWS * EMBD];
__device__ float g_V[MROWS * EMBD];
__device__ float g_A[MROWS * EMBD];
__device__ float g_X[MROWS * EMBD];        // tf32-rounded x
__device__ float g_W[4 * EMBD * EMBD];     // tf32-rounded Wq,Wk,Wv,Wo

__device__ __forceinline__ unsigned f2tf(float x) {
    unsigned u;
    asm("cvt.rna.tf32.f32 %0, %1;" : "=r"(u) : "f"(x));
    return u;
}

__device__ __forceinline__ void mma8(float* c, const unsigned* a, const unsigned* b) {
    asm volatile(
        "mma.sync.aligned.m16n8k8.row.col.f32.tf32.tf32.f32 "
        "{%0,%1,%2,%3}, {%4,%5,%6,%7}, {%8,%9}, {%0,%1,%2,%3};\n"
        : "+f"(c[0]), "+f"(c[1]), "+f"(c[2]), "+f"(c[3])
        : "r"(a[0]), "r"(a[1]), "r"(a[2]), "r"(a[3]),
          "r"(b[0]), "r"(b[1]));
}

__device__ __forceinline__ uint32_t s2u(const void* p) {
    return (uint32_t)__cvta_generic_to_shared(p);
}
#define CP16(dst, src) \
    asm volatile("cp.async.cg.shared.global [%0], [%1], 16;\n" :: "r"(dst), "l"(src))
#define CP_COMMIT() asm volatile("cp.async.commit_group;\n" ::: "memory")

// ---------------------------------------------------------------------------
// Pre-round fp32 -> tf32 bit pattern (elementwise, float4 vectorized)
// ---------------------------------------------------------------------------
__global__ __launch_bounds__(256) void round4(
    const float4* __restrict__ in, float4* __restrict__ out, int n4)
{
    int i = blockIdx.x * 256 + threadIdx.x;
    if (i < n4) {
        float4 v = in[i];
        v.x = __uint_as_float(f2tf(v.x));
        v.y = __uint_as_float(f2tf(v.y));
        v.z = __uint_as_float(f2tf(v.z));
        v.w = __uint_as_float(f2tf(v.w));
        out[i] = v;
    }
}

// ---------------------------------------------------------------------------
// TF32 GEMM body: C[M=8192,N=1024] = A @ B, CTA tile 128x128x32,
// cp.async 2-stage pipeline. 256 threads = 8 warps (4m x 2n).
// Inputs must already be tf32-rounded.
// ---------------------------------------------------------------------------
#define BK 32
#define ASTR 36
#define BSTR 136
#define ASZ (128 * ASTR)   // 4608 uints
#define BSZ (BK * BSTR)    // 4352 uints
#define GSMEM ((ASZ + BSZ) * 2 * 4)  // 71680 bytes

template<bool ROUND>
__device__ __forceinline__ void gemm_body(
    const float* __restrict__ A, const float* __restrict__ B, float* __restrict__ C)
{
    extern __shared__ unsigned sg[];
    unsigned* As = sg;             // 2 stages
    unsigned* Bs = sg + 2 * ASZ;   // 2 stages

    const int tid  = threadIdx.x;
    const int warp = tid >> 5;
    const int lane = tid & 31;
    const int l4   = lane >> 2;
    const int lm4  = lane & 3;
    const int wm0  = (warp >> 1) * 32;
    const int wn0  = (warp & 1) * 64;
    const int m0   = blockIdx.y * 128;
    const int n0   = blockIdx.x * 128;
    const int K = EMBD, N = EMBD;

    float acc[2][8][4];
    #pragma unroll
    for (int mi = 0; mi < 2; mi++)
        #pragma unroll
        for (int ni = 0; ni < 8; ni++)
            #pragma unroll
            for (int q = 0; q < 4; q++) acc[mi][ni][q] = 0.0f;

    auto load_stage = [&](int s, int k0) {
        #pragma unroll
        for (int t = 0; t < 4; t++) {
            int idx = tid + t * 256;
            int r = idx >> 3;
            int c = (idx & 7) * 4;
            CP16(s2u(&As[s * ASZ + r * ASTR + c]),
                 A + (size_t)(m0 + r) * K + k0 + c);
        }
        #pragma unroll
        for (int t = 0; t < 4; t++) {
            int idx = tid + t * 256;
            int r = idx >> 5;
            int c = (idx & 31) * 4;
            CP16(s2u(&Bs[s * BSZ + r * BSTR + c]),
                 B + (size_t)(k0 + r) * N + n0 + c);
        }
    };

    load_stage(0, 0);
    CP_COMMIT();

    const int KT = K / BK;  // 32
    for (int kt = 0; kt < KT; kt++) {
        if (kt + 1 < KT) {
            load_stage((kt + 1) & 1, (kt + 1) * BK);
            CP_COMMIT();
            asm volatile("cp.async.wait_group 1;\n" ::: "memory");
        } else {
            asm volatile("cp.async.wait_group 0;\n" ::: "memory");
        }
        __syncthreads();

        const unsigned* Ast = &As[(kt & 1) * ASZ];
        const unsigned* Bst = &Bs[(kt & 1) * BSZ];
        #pragma unroll
        for (int kk = 0; kk < BK; kk += 8) {
            unsigned a[2][4];
            #pragma unroll
            for (int mi = 0; mi < 2; mi++) {
                int rb = wm0 + mi * 16;
                a[mi][0] = Ast[(rb + l4)     * ASTR + kk + lm4];
                a[mi][1] = Ast[(rb + l4 + 8) * ASTR + kk + lm4];
                a[mi][2] = Ast[(rb + l4)     * ASTR + kk + lm4 + 4];
                a[mi][3] = Ast[(rb + l4 + 8) * ASTR + kk + lm4 + 4];
            }
            #pragma unroll
            for (int ni = 0; ni < 8; ni++) {
                unsigned b[2];
                int cb = wn0 + ni * 8;
                b[0] = Bst[(kk + lm4)     * BSTR + cb + l4];
                b[1] = Bst[(kk + lm4 + 4) * BSTR + cb + l4];
                mma8(acc[0][ni], a[0], b);
                mma8(acc[1][ni], a[1], b);
            }
        }
        __syncthreads();
    }

    #pragma unroll
    for (int mi = 0; mi < 2; mi++) {
        #pragma unroll
        for (int ni = 0; ni < 8; ni++) {
            int row = m0 + wm0 + mi * 16 + l4;
            int col = n0 + wn0 + ni * 8 + lm4 * 2;
            float v0 = acc[mi][ni][0], v1 = acc[mi][ni][1];
            float v2 = acc[mi][ni][2], v3 = acc[mi][ni][3];
            if (ROUND) {
                v0 = __uint_as_float(f2tf(v0));
                v1 = __uint_as_float(f2tf(v1));
                v2 = __uint_as_float(f2tf(v2));
                v3 = __uint_as_float(f2tf(v3));
            }
            *(float2*)&C[(size_t)row * EMBD + col] = make_float2(v0, v1);
            *(float2*)&C[(size_t)(row + 8) * EMBD + col] = make_float2(v2, v3);
        }
    }
}

// Fused QKV: grid.z selects weight/output (outputs rounded for attention)
__global__ __launch_bounds__(256, 2) void gemm_qkv(
    const float* __restrict__ X,
    const float* __restrict__ W0, const float* __restrict__ W1, const float* __restrict__ W2,
    float* __restrict__ C0, float* __restrict__ C1, float* __restrict__ C2)
{
    const float* W = (blockIdx.z == 0) ? W0 : (blockIdx.z == 1) ? W1 : W2;
    float*       C = (blockIdx.z == 0) ? C0 : (blockIdx.z == 1) ? C1 : C2;
    gemm_body<true>(X, W, C);
}

// Final projection: full fp32 output
__global__ __launch_bounds__(256, 2) void gemm_out(
    const float* __restrict__ A, const float* __restrict__ W, float* __restrict__ C)
{
    gemm_body<false>(A, W, C);
}

// ---------------------------------------------------------------------------
// Causal flash attention (TF32 mma). One CTA = 128 q-rows of one (b,h).
// 256 threads = 8 warps; warp w owns q-rows [w*16, w*16+16) of the tile.
// Inputs pre-rounded to tf32; output rounded for the final GEMM.
// ---------------------------------------------------------------------------
#define QST 68
#define KST 68
#define VST 72
#define PST 68
#define ATTN_SMEM ((128*QST + 64*KST + 64*VST + 128*PST) * 4)  // 105472 B

__global__ __launch_bounds__(256, 2) void attn_flash(
    const float* __restrict__ Q, const float* __restrict__ K,
    const float* __restrict__ V, float* __restrict__ O)
{
    extern __shared__ unsigned sa[];
    unsigned* Qs = sa;
    unsigned* Ks = Qs + 128 * QST;
    unsigned* Vs = Ks + 64 * KST;
    unsigned* Ps = Vs + 64 * VST;

    const int tid  = threadIdx.x;
    const int warp = tid >> 5;
    const int lane = tid & 31;
    const int l4   = lane >> 2;
    const int lm4  = lane & 3;
    const int w16  = warp * 16;

    const int qb = (gridDim.x - 1) - blockIdx.x;   // longest blocks first
    const int q0 = qb * 128;
    const int bh = blockIdx.y;
    const int b  = bh >> 4;
    const int h  = bh & 15;
    const size_t headoff = (size_t)b * SEQ * EMBD + (size_t)h * HDIM;
    const float SCALE = 0.125f;   // 1/sqrt(64)

    // Load Q tile (128 x 64), already tf32-rounded -> raw copy
    #pragma unroll
    for (int t = 0; t < 8; t++) {
        int idx = tid + t * 256;
        int r = idx >> 4;
        int c = (idx & 15) * 4;
        *(uint4*)&Qs[r * QST + c] =
            *(const uint4*)(Q + headoff + (size_t)(q0 + r) * EMBD + c);
    }

    float m0 = -INFINITY, m1 = -INFINITY, l0 = 0.0f, l1 = 0.0f;
    float o[8][4];
    #pragma unroll
    for (int ni = 0; ni < 8; ni++)
        #pragma unroll
        for (int q = 0; q < 4; q++) o[ni][q] = 0.0f;

    const int jmax = 2 * qb + 1;
    for (int j = 0; j <= jmax; j++) {
        __syncthreads();
        #pragma unroll
        for (int t = 0; t < 4; t++) {
            int idx = tid + t * 256;
            int r = idx >> 4;
            int c = (idx & 15) * 4;
            *(uint4*)&Ks[r * KST + c] =
                *(const uint4*)(K + headoff + (size_t)(j * 64 + r) * EMBD + c);
            *(uint4*)&Vs[r * VST + c] =
                *(const uint4*)(V + headoff + (size_t)(j * 64 + r) * EMBD + c);
        }
        __syncthreads();

        // S = Q K^T  (warp: 16 q-rows x 64 key-cols)
        float s[8][4];
        #pragma unroll
        for (int ni = 0; ni < 8; ni++)
            #pragma unroll
            for (int q = 0; q < 4; q++) s[ni][q] = 0.0f;

        #pragma unroll
        for (int kk = 0; kk < 64; kk += 8) {
            unsigned a[4];
            a[0] = Qs[(w16 + l4)     * QST + kk + lm4];
            a[1] = Qs[(w16 + l4 + 8) * QST + kk + lm4];
            a[2] = Qs[(w16 + l4)     * QST + kk + lm4 + 4];
            a[3] = Qs[(w16 + l4 + 8) * QST + kk + lm4 + 4];
            #pragma unroll
            for (int ni = 0; ni < 8; ni++) {
                unsigned bf[2];
                bf[0] = Ks[(ni * 8 + l4) * KST + kk + lm4];
                bf[1] = Ks[(ni * 8 + l4) * KST + kk + lm4 + 4];
                mma8(s[ni], a, bf);
            }
        }

        // Scale + causal mask + online softmax
        const int grow0 = q0 + w16 + l4;
        const int grow1 = grow0 + 8;
        const bool pm = (j * 64 + 63) > (q0 + w16);  // tile may need masking
        float rm0 = -INFINITY, rm1 = -INFINITY;
        #pragma unroll
        for (int ni = 0; ni < 8; ni++) {
            int gc = j * 64 + ni * 8 + lm4 * 2;
            float v0 = s[ni][0] * SCALE;
            float v1 = s[ni][1] * SCALE;
            float v2 = s[ni][2] * SCALE;
            float v3 = s[ni][3] * SCALE;
            if (pm) {
                if (gc     > grow0) v0 = -INFINITY;
                if (gc + 1 > grow0) v1 = -INFINITY;
                if (gc     > grow1) v2 = -INFINITY;
                if (gc + 1 > grow1) v3 = -INFINITY;
            }
            s[ni][0] = v0; s[ni][1] = v1; s[ni][2] = v2; s[ni][3] = v3;
            rm0 = fmaxf(rm0, fmaxf(v0, v1));
            rm1 = fmaxf(rm1, fmaxf(v2, v3));
        }
        #pragma unroll
        for (int off = 1; off < 4; off <<= 1) {
            rm0 = fmaxf(rm0, __shfl_xor_sync(0xffffffffu, rm0, off));
            rm1 = fmaxf(rm1, __shfl_xor_sync(0xffffffffu, rm1, off));
        }

        float nm0 = fmaxf(m0, rm0);
        float nm1 = fmaxf(m1, rm1);
        float a0 = __expf(m0 - nm0);
        float a1 = __expf(m1 - nm1);
        m0 = nm0; m1 = nm1;

        float rs0 = 0.0f, rs1 = 0.0f;
        #pragma unroll
        for (int ni = 0; ni < 8; ni++) {
            float p0 = __expf(s[ni][0] - nm0);
            float p1 = __expf(s[ni][1] - nm0);
            float p2 = __expf(s[ni][2] - nm1);
            float p3 = __expf(s[ni][3] - nm1);
            rs0 += p0 + p1;
            rs1 += p2 + p3;
            int col = ni * 8 + lm4 * 2;
            Ps[(w16 + l4)     * PST + col]     = f2tf(p0);
            Ps[(w16 + l4)     * PST + col + 1] = f2tf(p1);
            Ps[(w16 + l4 + 8) * PST + col]     = f2tf(p2);
            Ps[(w16 + l4 + 8) * PST + col + 1] = f2tf(p3);
            o[ni][0] *= a0; o[ni][1] *= a0;
            o[ni][2] *= a1; o[ni][3] *= a1;
        }
        #pragma unroll
        for (int off = 1; off < 4; off <<= 1) {
            rs0 += __shfl_xor_sync(0xffffffffu, rs0, off);
            rs1 += __shfl_xor_sync(0xffffffffu, rs1, off);
        }
        l0 = a0 * l0 + rs0;
        l1 = a1 * l1 + rs1;

        __syncwarp();

        // O += P @ V
        #pragma unroll
        for (int kk = 0; kk < 64; kk += 8) {
            unsigned a[4];
            a[0] = Ps[(w16 + l4)     * PST + kk + lm4];
            a[1] = Ps[(w16 + l4 + 8) * PST + kk + lm4];
            a[2] = Ps[(w16 + l4)     * PST + kk + lm4 + 4];
            a[3] = Ps[(w16 + l4 + 8) * PST + kk + lm4 + 4];
            #pragma unroll
            for (int ni = 0; ni < 8; ni++) {
                unsigned bf[2];
                bf[0] = Vs[(kk + lm4)     * VST + ni * 8 + l4];
                bf[1] = Vs[(kk + lm4 + 4) * VST + ni * 8 + l4];
                mma8(o[ni], a, bf);
            }
        }
    }

    // Epilogue: normalize, round to tf32 (feeds final GEMM), store
    float i0 = 1.0f / l0;
    float i1 = 1.0f / l1;
    #pragma unroll
    for (int ni = 0; ni < 8; ni++) {
        int gr = b * SEQ + q0 + w16 + l4;
        int gc = h * HDIM + ni * 8 + lm4 * 2;
        *(float2*)&O[(size_t)gr * EMBD + gc] = make_float2(
            __uint_as_float(f2tf(o[ni][0] * i0)),
            __uint_as_float(f2tf(o[ni][1] * i0)));
        *(float2*)&O[(size_t)(gr + 8) * EMBD + gc] = make_float2(
            __uint_as_float(f2tf(o[ni][2] * i1)),
            __uint_as_float(f2tf(o[ni][3] * i1)));
    }
}

// ---------------------------------------------------------------------------
// Launch
// ---------------------------------------------------------------------------
extern "C" void kernel_launch(void* const* d_in, const int* in_sizes, int n_in,
                              void* d_out, int out_size)
{
    const float* x  = (const float*)d_in[0];
    const float* Wq = (const float*)d_in[1];
    const float* Wk = (const float*)d_in[2];
    const float* Wv = (const float*)d_in[3];
    const float* Wo = (const float*)d_in[4];
    float* out = (float*)d_out;

    float *Qp, *Kp, *Vp, *Ap, *Xp, *Wp;
    cudaGetSymbolAddress((void**)&Qp, g_Q);
    cudaGetSymbolAddress((void**)&Kp, g_K);
    cudaGetSymbolAddress((void**)&Vp, g_V);
    cudaGetSymbolAddress((void**)&Ap, g_A);
    cudaGetSymbolAddress((void**)&Xp, g_X);
    cudaGetSymbolAddress((void**)&Wp, g_W);

    cudaFuncSetAttribute(gemm_qkv,  cudaFuncAttributeMaxDynamicSharedMemorySize, GSMEM);
    cudaFuncSetAttribute(gemm_out,  cudaFuncAttributeMaxDynamicSharedMemorySize, GSMEM);
    cudaFuncSetAttribute(attn_flash, cudaFuncAttributeMaxDynamicSharedMemorySize, ATTN_SMEM);

    const int WN4 = EMBD * EMBD / 4;       // 262144
    const int XN4 = MROWS * EMBD / 4;      // 2097152

    round4<<<XN4 / 256, 256>>>((const float4*)x,  (float4*)Xp, XN4);
    round4<<<WN4 / 256, 256>>>((const float4*)Wq, (float4*)(Wp + 0 * EMBD * EMBD), WN4);
    round4<<<WN4 / 256, 256>>>((const float4*)Wk, (float4*)(Wp + 1 * EMBD * EMBD), WN4);
    round4<<<WN4 / 256, 256>>>((const float4*)Wv, (float4*)(Wp + 2 * EMBD * EMBD), WN4);
    round4<<<WN4 / 256, 256>>>((const float4*)Wo, (float4*)(Wp + 3 * EMBD * EMBD), WN4);

    dim3 gqkv(EMBD / 128, MROWS / 128, 3);   // (8, 64, 3)
    gemm_qkv<<<gqkv, 256, GSMEM>>>(Xp,
        Wp + 0 * EMBD * EMBD, Wp + 1 * EMBD * EMBD, Wp + 2 * EMBD * EMBD,
        Qp, Kp, Vp);

    dim3 ga(SEQ / 128, BATCH * NHEAD);       // (16, 64)
    attn_flash<<<ga, 256, ATTN_SMEM>>>(Qp, Kp, Vp, Ap);

    dim3 go(EMBD / 128, MROWS / 128);        // (8, 64)
    gemm_out<<<go, 256, GSMEM>>>(Ap, Wp + 3 * EMBD * EMBD, out);
}

// round 3
// speedup vs baseline: 1.1752x; 1.0866x over previous
#include <cuda_runtime.h>
#include <math.h>
#include <stdint.h>

// ---------------------------------------------------------------------------
// MultiHeadAttention: x@Wq/Wk/Wv -> causal flash attention -> @Wo
// B=4, S=2048, E=1024, H=16, Hs=64. fp32 I/O, TF32 tensor-core math.
// R3: in-GEMM A-fragment tf32 cvt (no x pre-pass), 3-stage GEMM pipeline,
//     attention with double-buffered cp.async K/V + P-via-shuffle (no P smem).
// ---------------------------------------------------------------------------

#define BATCH 4
#define SEQ   2048
#define EMBD  1024
#define NHEAD 16
#define HDIM  64
#define MROWS (BATCH*SEQ)   // 8192

__device__ float g_Q[MROWS * EMBD];
__device__ float g_K[MROWS * EMBD];
__device__ float g_V[MROWS * EMBD];
__device__ float g_A[MROWS * EMBD];
__device__ float g_W[4 * EMBD * EMBD];     // tf32-rounded Wq,Wk,Wv,Wo

__device__ __forceinline__ unsigned f2tf(float x) {
    unsigned u;
    asm("cvt.rna.tf32.f32 %0, %1;" : "=r"(u) : "f"(x));
    return u;
}

__device__ __forceinline__ void mma8(float* c, const unsigned* a, const unsigned* b) {
    asm volatile(
        "mma.sync.aligned.m16n8k8.row.col.f32.tf32.tf32.f32 "
        "{%0,%1,%2,%3}, {%4,%5,%6,%7}, {%8,%9}, {%0,%1,%2,%3};\n"
        : "+f"(c[0]), "+f"(c[1]), "+f"(c[2]), "+f"(c[3])
        : "r"(a[0]), "r"(a[1]), "r"(a[2]), "r"(a[3]),
          "r"(b[0]), "r"(b[1]));
}

__device__ __forceinline__ uint32_t s2u(const void* p) {
    return (uint32_t)__cvta_generic_to_shared(p);
}
#define CP16(dst, src) \
    asm volatile("cp.async.cg.shared.global [%0], [%1], 16;\n" :: "r"(dst), "l"(src))
#define CP_COMMIT()  asm volatile("cp.async.commit_group;\n" ::: "memory")
#define CP_WAIT(n)   asm volatile("cp.async.wait_group %0;\n" :: "n"(n) : "memory")

// ---------------------------------------------------------------------------
// Round all 4 weight matrices to tf32 in one launch. grid=(1024,4).
// ---------------------------------------------------------------------------
__global__ __launch_bounds__(256) void round_w(
    const float4* __restrict__ w0, const float4* __restrict__ w1,
    const float4* __restrict__ w2, const float4* __restrict__ w3,
    float4* __restrict__ out)
{
    const float4* in = (blockIdx.y == 0) ? w0 : (blockIdx.y == 1) ? w1
                     : (blockIdx.y == 2) ? w2 : w3;
    int i = blockIdx.x * 256 + threadIdx.x;
    float4 v = in[i];
    v.x = __uint_as_float(f2tf(v.x));
    v.y = __uint_as_float(f2tf(v.y));
    v.z = __uint_as_float(f2tf(v.z));
    v.w = __uint_as_float(f2tf(v.w));
    out[(size_t)blockIdx.y * (EMBD * EMBD / 4) + i] = v;
}

// ---------------------------------------------------------------------------
// TF32 GEMM body: C[8192,1024] = A @ B, CTA tile 128x128x32,
// 3-stage cp.async pipeline, one barrier per K-step.
// CVT_A: A is raw fp32, cvt fragments in-register. ROUND: round output.
// ---------------------------------------------------------------------------
#define BK 32
#define ASTR 36
#define BSTR 136
#define ASZ (128 * ASTR)   // 4608 uints
#define BSZ (BK * BSTR)    // 4352 uints
#define GSTAGES 3
#define GSMEM ((ASZ + BSZ) * GSTAGES * 4)  // 107520 bytes

template<bool CVT_A, bool ROUND>
__device__ __forceinline__ void gemm_body(
    const float* __restrict__ A, const float* __restrict__ B, float* __restrict__ C)
{
    extern __shared__ unsigned sg[];
    unsigned* As = sg;
    unsigned* Bs = sg + GSTAGES * ASZ;

    const int tid  = threadIdx.x;
    const int warp = tid >> 5;
    const int lane = tid & 31;
    const int l4   = lane >> 2;
    const int lm4  = lane & 3;
    const int wm0  = (warp >> 1) * 32;
    const int wn0  = (warp & 1) * 64;
    const int m0   = blockIdx.y * 128;
    const int n0   = blockIdx.x * 128;
    const int K = EMBD, N = EMBD;

    float acc[2][8][4];
    #pragma unroll
    for (int mi = 0; mi < 2; mi++)
        #pragma unroll
        for (int ni = 0; ni < 8; ni++)
            #pragma unroll
            for (int q = 0; q < 4; q++) acc[mi][ni][q] = 0.0f;

    auto load_stage = [&](int s, int k0) {
        #pragma unroll
        for (int t = 0; t < 4; t++) {
            int idx = tid + t * 256;
            int r = idx >> 3;
            int c = (idx & 7) * 4;
            CP16(s2u(&As[s * ASZ + r * ASTR + c]),
                 A + (size_t)(m0 + r) * K + k0 + c);
        }
        #pragma unroll
        for (int t = 0; t < 4; t++) {
            int idx = tid + t * 256;
            int r = idx >> 5;
            int c = (idx & 31) * 4;
            CP16(s2u(&Bs[s * BSZ + r * BSTR + c]),
                 B + (size_t)(k0 + r) * N + n0 + c);
        }
        CP_COMMIT();
    };

    load_stage(0, 0);
    load_stage(1, BK);

    const int KT = K / BK;  // 32
    int s_cur = 0, s_nxt = 2;
    for (int kt = 0; kt < KT; kt++) {
        CP_WAIT(1);
        __syncthreads();
        if (kt + 2 < KT) {
            load_stage(s_nxt, (kt + 2) * BK);
            if (++s_nxt == GSTAGES) s_nxt = 0;
        }

        const unsigned* Ast = &As[s_cur * ASZ];
        const unsigned* Bst = &Bs[s_cur * BSZ];
        if (++s_cur == GSTAGES) s_cur = 0;

        #pragma unroll
        for (int kk = 0; kk < BK; kk += 8) {
            unsigned a[2][4];
            #pragma unroll
            for (int mi = 0; mi < 2; mi++) {
                int rb = wm0 + mi * 16;
                unsigned r0 = Ast[(rb + l4)     * ASTR + kk + lm4];
                unsigned r1 = Ast[(rb + l4 + 8) * ASTR + kk + lm4];
                unsigned r2 = Ast[(rb + l4)     * ASTR + kk + lm4 + 4];
                unsigned r3 = Ast[(rb + l4 + 8) * ASTR + kk + lm4 + 4];
                if (CVT_A) {
                    r0 = f2tf(__uint_as_float(r0));
                    r1 = f2tf(__uint_as_float(r1));
                    r2 = f2tf(__uint_as_float(r2));
                    r3 = f2tf(__uint_as_float(r3));
                }
                a[mi][0] = r0; a[mi][1] = r1; a[mi][2] = r2; a[mi][3] = r3;
            }
            #pragma unroll
            for (int ni = 0; ni < 8; ni++) {
                unsigned b[2];
                int cb = wn0 + ni * 8;
                b[0] = Bst[(kk + lm4)     * BSTR + cb + l4];
                b[1] = Bst[(kk + lm4 + 4) * BSTR + cb + l4];
                mma8(acc[0][ni], a[0], b);
                mma8(acc[1][ni], a[1], b);
            }
        }
    }

    #pragma unroll
    for (int mi = 0; mi < 2; mi++) {
        #pragma unroll
        for (int ni = 0; ni < 8; ni++) {
            int row = m0 + wm0 + mi * 16 + l4;
            int col = n0 + wn0 + ni * 8 + lm4 * 2;
            float v0 = acc[mi][ni][0], v1 = acc[mi][ni][1];
            float v2 = acc[mi][ni][2], v3 = acc[mi][ni][3];
            if (ROUND) {
                v0 = __uint_as_float(f2tf(v0));
                v1 = __uint_as_float(f2tf(v1));
                v2 = __uint_as_float(f2tf(v2));
                v3 = __uint_as_float(f2tf(v3));
            }
            *(float2*)&C[(size_t)row * EMBD + col] = make_float2(v0, v1);
            *(float2*)&C[(size_t)(row + 8) * EMBD + col] = make_float2(v2, v3);
        }
    }
}

__global__ __launch_bounds__(256, 2) void gemm_qkv(
    const float* __restrict__ X, const float* __restrict__ W,
    float* __restrict__ C0, float* __restrict__ C1, float* __restrict__ C2)
{
    const float* Wz = W + (size_t)blockIdx.z * EMBD * EMBD;
    float* C = (blockIdx.z == 0) ? C0 : (blockIdx.z == 1) ? C1 : C2;
    gemm_body<true, true>(X, Wz, C);
}

__global__ __launch_bounds__(256, 2) void gemm_out(
    const float* __restrict__ A, const float* __restrict__ W, float* __restrict__ C)
{
    gemm_body<false, false>(A, W, C);
}

// ---------------------------------------------------------------------------
// Causal flash attention. One CTA = 128 q-rows of one (b,h), 256 threads.
// K/V double-buffered via cp.async; P converted C->A layout via shuffles.
// ---------------------------------------------------------------------------
#define QST 68
#define KST 68
#define VST 72
#define KSZ (64 * KST)
#define VSZ (64 * VST)
#define ATTN_SMEM ((128*QST + 2*KSZ + 2*VSZ) * 4)  // 106496 bytes

__global__ __launch_bounds__(256, 2) void attn_flash(
    const float* __restrict__ Q, const float* __restrict__ K,
    const float* __restrict__ V, float* __restrict__ O)
{
    extern __shared__ unsigned sa[];
    unsigned* Qs = sa;
    unsigned* Ks = Qs + 128 * QST;
    unsigned* Vs = Ks + 2 * KSZ;

    const int tid  = threadIdx.x;
    const int warp = tid >> 5;
    const int lane = tid & 31;
    const int l4   = lane >> 2;
    const int lm4  = lane & 3;
    const int w16  = warp * 16;

    const int qb = (gridDim.x - 1) - blockIdx.x;   // longest blocks first
    const int q0 = qb * 128;
    const int bh = blockIdx.y;
    const int b  = bh >> 4;
    const int h  = bh & 15;
    const size_t headoff = (size_t)b * SEQ * EMBD + (size_t)h * HDIM;
    const float SCALE = 0.125f;

    // shuffle sources for C->A layout conversion (within 4-lane quad)
    const int src1 = (lane & 28) | (lm4 >> 1);
    const int src2 = src1 + 2;
    const bool par = (lm4 & 1);

    // Load Q tile (128 x 64), pre-rounded -> raw copy
    #pragma unroll
    for (int t = 0; t < 8; t++) {
        int idx = tid + t * 256;
        int r = idx >> 4;
        int c = (idx & 15) * 4;
        *(uint4*)&Qs[r * QST + c] =
            *(const uint4*)(Q + headoff + (size_t)(q0 + r) * EMBD + c);
    }

    auto load_kv = [&](int j, int s) {
        #pragma unroll
        for (int t = 0; t < 4; t++) {
            int idx = tid + t * 256;
            int r = idx >> 4;
            int c = (idx & 15) * 4;
            CP16(s2u(&Ks[s * KSZ + r * KST + c]),
                 K + headoff + (size_t)(j * 64 + r) * EMBD + c);
            CP16(s2u(&Vs[s * VSZ + r * VST + c]),
                 V + headoff + (size_t)(j * 64 + r) * EMBD + c);
        }
        CP_COMMIT();
    };

    float m0 = -INFINITY, m1 = -INFINITY, l0 = 0.0f, l1 = 0.0f;
    float o[8][4];
    #pragma unroll
    for (int ni = 0; ni < 8; ni++)
        #pragma unroll
        for (int q = 0; q < 4; q++) o[ni][q] = 0.0f;

    const int jmax = 2 * qb + 1;
    load_kv(0, 0);

    for (int j = 0; j <= jmax; j++) {
        CP_WAIT(0);
        __syncthreads();
        if (j < jmax) load_kv(j + 1, (j + 1) & 1);

        const unsigned* Kst = &Ks[(j & 1) * KSZ];
        const unsigned* Vst = &Vs[(j & 1) * VSZ];

        // S = Q K^T  (warp: 16 q-rows x 64 key-cols)
        float s[8][4];
        #pragma unroll
        for (int ni = 0; ni < 8; ni++)
            #pragma unroll
            for (int q = 0; q < 4; q++) s[ni][q] = 0.0f;

        #pragma unroll
        for (int kk = 0; kk < 64; kk += 8) {
            unsigned a[4];
            a[0] = Qs[(w16 + l4)     * QST + kk + lm4];
            a[1] = Qs[(w16 + l4 + 8) * QST + kk + lm4];
            a[2] = Qs[(w16 + l4)     * QST + kk + lm4 + 4];
            a[3] = Qs[(w16 + l4 + 8) * QST + kk + lm4 + 4];
            #pragma unroll
            for (int ni = 0; ni < 8; ni++) {
                unsigned bf[2];
                bf[0] = Kst[(ni * 8 + l4) * KST + kk + lm4];
                bf[1] = Kst[(ni * 8 + l4) * KST + kk + lm4 + 4];
                mma8(s[ni], a, bf);
            }
        }

        // Scale + causal mask + online softmax (p left in s[][] as fp32)
        const int grow0 = q0 + w16 + l4;
        const int grow1 = grow0 + 8;
        const bool pm = (j * 64 + 63) > (q0 + w16);
        float rm0 = -INFINITY, rm1 = -INFINITY;
        #pragma unroll
        for (int ni = 0; ni < 8; ni++) {
            int gc = j * 64 + ni * 8 + lm4 * 2;
            float v0 = s[ni][0] * SCALE;
            float v1 = s[ni][1] * SCALE;
            float v2 = s[ni][2] * SCALE;
            float v3 = s[ni][3] * SCALE;
            if (pm) {
                if (gc     > grow0) v0 = -INFINITY;
                if (gc + 1 > grow0) v1 = -INFINITY;
                if (gc     > grow1) v2 = -INFINITY;
                if (gc + 1 > grow1) v3 = -INFINITY;
            }
            s[ni][0] = v0; s[ni][1] = v1; s[ni][2] = v2; s[ni][3] = v3;
            rm0 = fmaxf(rm0, fmaxf(v0, v1));
            rm1 = fmaxf(rm1, fmaxf(v2, v3));
        }
        #pragma unroll
        for (int off = 1; off < 4; off <<= 1) {
            rm0 = fmaxf(rm0, __shfl_xor_sync(0xffffffffu, rm0, off));
            rm1 = fmaxf(rm1, __shfl_xor_sync(0xffffffffu, rm1, off));
        }

        float nm0 = fmaxf(m0, rm0);
        float nm1 = fmaxf(m1, rm1);
        float a0 = __expf(m0 - nm0);
        float a1 = __expf(m1 - nm1);
        m0 = nm0; m1 = nm1;

        float rs0 = 0.0f, rs1 = 0.0f;
        #pragma unroll
        for (int ni = 0; ni < 8; ni++) {
            float p0 = __expf(s[ni][0] - nm0);
            float p1 = __expf(s[ni][1] - nm0);
            float p2 = __expf(s[ni][2] - nm1);
            float p3 = __expf(s[ni][3] - nm1);
            rs0 += p0 + p1;
            rs1 += p2 + p3;
            s[ni][0] = p0; s[ni][1] = p1; s[ni][2] = p2; s[ni][3] = p3;
            o[ni][0] *= a0; o[ni][1] *= a0;
            o[ni][2] *= a1; o[ni][3] *= a1;
        }
        #pragma unroll
        for (int off = 1; off < 4; off <<= 1) {
            rs0 += __shfl_xor_sync(0xffffffffu, rs0, off);
            rs1 += __shfl_xor_sync(0xffffffffu, rs1, off);
        }
        l0 = a0 * l0 + rs0;
        l1 = a1 * l1 + rs1;

        // O += P @ V.  P fragments built from s[][] via intra-quad shuffles.
        #pragma unroll
        for (int kb = 0; kb < 8; kb++) {
            unsigned u0 = f2tf(s[kb][0]);
            unsigned u1 = f2tf(s[kb][1]);
            unsigned u2 = f2tf(s[kb][2]);
            unsigned u3 = f2tf(s[kb][3]);
            unsigned t0 = __shfl_sync(0xffffffffu, u0, src1);
            unsigned t1 = __shfl_sync(0xffffffffu, u1, src1);
            unsigned t2 = __shfl_sync(0xffffffffu, u2, src1);
            unsigned t3 = __shfl_sync(0xffffffffu, u3, src1);
            unsigned t4 = __shfl_sync(0xffffffffu, u0, src2);
            unsigned t5 = __shfl_sync(0xffffffffu, u1, src2);
            unsigned t6 = __shfl_sync(0xffffffffu, u2, src2);
            unsigned t7 = __shfl_sync(0xffffffffu, u3, src2);
            unsigned a[4];
            a[0] = par ? t1 : t0;
            a[1] = par ? t3 : t2;
            a[2] = par ? t5 : t4;
            a[3] = par ? t7 : t6;
            const int kk = kb * 8;
            #pragma unroll
            for (int ni = 0; ni < 8; ni++) {
                unsigned bf[2];
                bf[0] = Vst[(kk + lm4)     * VST + ni * 8 + l4];
                bf[1] = Vst[(kk + lm4 + 4) * VST + ni * 8 + l4];
                mma8(o[ni], a, bf);
            }
        }
    }

    // Epilogue: normalize, round to tf32 (feeds final GEMM), store
    float i0 = 1.0f / l0;
    float i1 = 1.0f / l1;
    #pragma unroll
    for (int ni = 0; ni < 8; ni++) {
        int gr = b * SEQ + q0 + w16 + l4;
        int gc = h * HDIM + ni * 8 + lm4 * 2;
        *(float2*)&O[(size_t)gr * EMBD + gc] = make_float2(
            __uint_as_float(f2tf(o[ni][0] * i0)),
            __uint_as_float(f2tf(o[ni][1] * i0)));
        *(float2*)&O[(size_t)(gr + 8) * EMBD + gc] = make_float2(
            __uint_as_float(f2tf(o[ni][2] * i1)),
            __uint_as_float(f2tf(o[ni][3] * i1)));
    }
}

// ---------------------------------------------------------------------------
// Launch
// ---------------------------------------------------------------------------
extern "C" void kernel_launch(void* const* d_in, const int* in_sizes, int n_in,
                              void* d_out, int out_size)
{
    const float* x  = (const float*)d_in[0];
    const float* Wq = (const float*)d_in[1];
    const float* Wk = (const float*)d_in[2];
    const float* Wv = (const float*)d_in[3];
    const float* Wo = (const float*)d_in[4];
    float* out = (float*)d_out;

    float *Qp, *Kp, *Vp, *Ap, *Wp;
    cudaGetSymbolAddress((void**)&Qp, g_Q);
    cudaGetSymbolAddress((void**)&Kp, g_K);
    cudaGetSymbolAddress((void**)&Vp, g_V);
    cudaGetSymbolAddress((void**)&Ap, g_A);
    cudaGetSymbolAddress((void**)&Wp, g_W);

    cudaFuncSetAttribute(gemm_qkv,   cudaFuncAttributeMaxDynamicSharedMemorySize, GSMEM);
    cudaFuncSetAttribute(gemm_out,   cudaFuncAttributeMaxDynamicSharedMemorySize, GSMEM);
    cudaFuncSetAttribute(attn_flash, cudaFuncAttributeMaxDynamicSharedMemorySize, ATTN_SMEM);

    const int WN4 = EMBD * EMBD / 4;  // 262144

    dim3 gw(WN4 / 256, 4);
    round_w<<<gw, 256>>>((const float4*)Wq, (const float4*)Wk,
                         (const float4*)Wv, (const float4*)Wo, (float4*)Wp);

    dim3 gqkv(EMBD / 128, MROWS / 128, 3);   // (8, 64, 3)
    gemm_qkv<<<gqkv, 256, GSMEM>>>(x, Wp, Qp, Kp, Vp);

    dim3 ga(SEQ / 128, BATCH * NHEAD);       // (16, 64)
    attn_flash<<<ga, 256, ATTN_SMEM>>>(Qp, Kp, Vp, Ap);

    dim3 go(EMBD / 128, MROWS / 128);        // (8, 64)
    gemm_out<<<go, 256, GSMEM>>>(Ap, Wp + 3 * (size_t)EMBD * EMBD, out);
}

// round 5
// speedup vs baseline: 1.2178x; 1.0362x over previous
#include <cuda_runtime.h>
#include <math.h>
#include <stdint.h>

// ---------------------------------------------------------------------------
// MultiHeadAttention: x@Wq/Wk/Wv -> causal flash attention -> @Wo
// B=4, S=2048, E=1024, H=16, Hs=64. fp32 I/O, TF32 tensor-core math.
// R5: base-ISA only (tcgen05 unavailable: harness PTX target is compute_103).
//     All mma operand fragments loaded via ldmatrix.x4 (LDSM) from K-major
//     smem tiles; weights pre-transposed+rounded; x cvt folded into GEMM.
// ---------------------------------------------------------------------------

#define BATCH 4
#define SEQ   2048
#define EMBD  1024
#define NHEAD 16
#define HDIM  64
#define MROWS (BATCH*SEQ)   // 8192

__device__ float g_Q[MROWS * EMBD];
__device__ float g_K[MROWS * EMBD];
__device__ float g_V[MROWS * EMBD];
__device__ float g_A[MROWS * EMBD];
__device__ float g_W[4 * EMBD * EMBD];     // tf32-rounded, TRANSPOSED [n][k]

__device__ __forceinline__ unsigned f2tf(float x) {
    unsigned u;
    asm("cvt.rna.tf32.f32 %0, %1;" : "=r"(u) : "f"(x));
    return u;
}

__device__ __forceinline__ void mma8(float* c, const unsigned* a, const unsigned* b) {
    asm volatile(
        "mma.sync.aligned.m16n8k8.row.col.f32.tf32.tf32.f32 "
        "{%0,%1,%2,%3}, {%4,%5,%6,%7}, {%8,%9}, {%0,%1,%2,%3};\n"
        : "+f"(c[0]), "+f"(c[1]), "+f"(c[2]), "+f"(c[3])
        : "r"(a[0]), "r"(a[1]), "r"(a[2]), "r"(a[3]),
          "r"(b[0]), "r"(b[1]));
}

__device__ __forceinline__ uint32_t s2u(const void* p) {
    return (uint32_t)__cvta_generic_to_shared(p);
}
#define CP16(dst, src) \
    asm volatile("cp.async.cg.shared.global [%0], [%1], 16;\n" :: "r"(dst), "l"(src))
#define CP_COMMIT()  asm volatile("cp.async.commit_group;\n" ::: "memory")
#define CP_WAIT(n)   asm volatile("cp.async.wait_group %0;\n" :: "n"(n) : "memory")

// ldmatrix x4: four 8x8 b16 matrices == four 8x4-tf32 sub-tiles.
#define LDSM4(r, addr) \
    asm volatile("ldmatrix.sync.aligned.m8n8.x4.shared.b16 {%0,%1,%2,%3}, [%4];" \
        : "=r"((r)[0]), "=r"((r)[1]), "=r"((r)[2]), "=r"((r)[3]) : "r"(addr))

// ---------------------------------------------------------------------------
// Weight pre-pass: round to tf32 + transpose to [n][k]
// ---------------------------------------------------------------------------
__global__ __launch_bounds__(256) void round_wt(
    const float* __restrict__ w0, const float* __restrict__ w1,
    const float* __restrict__ w2, const float* __restrict__ w3,
    float* __restrict__ out)
{
    __shared__ float t[32][33];
    const float* in = (blockIdx.z == 0) ? w0 : (blockIdx.z == 1) ? w1
                    : (blockIdx.z == 2) ? w2 : w3;
    float* o = out + (size_t)blockIdx.z * EMBD * EMBD;
    int bx = blockIdx.x * 32, by = blockIdx.y * 32;
    int tx = threadIdx.x & 31, ty = threadIdx.x >> 5;   // 32x8
    #pragma unroll
    for (int i = 0; i < 32; i += 8)
        t[ty + i][tx] = in[(size_t)(by + ty + i) * EMBD + bx + tx];
    __syncthreads();
    #pragma unroll
    for (int i = 0; i < 32; i += 8)
        o[(size_t)(bx + ty + i) * EMBD + by + tx] =
            __uint_as_float(f2tf(t[tx][ty + i]));
}

// ---------------------------------------------------------------------------
// TF32 GEMM: C[8192,1024] = A[m][k] @ Bt[n][k]^T. CTA tile 128x128x32.
// Both A and B smem tiles K-major [128 rows][36 words]; LDSM fragments.
// 256 threads = 8 warps (4m x 2n), 3-stage cp.async pipeline.
// ---------------------------------------------------------------------------
#define TSTR 36                       // tile row stride (words); 144B, 16B-mult
#define TILE_B (128 * TSTR * 4)       // 18432 bytes per tile
#define STG_BYTES (2 * TILE_B)        // A + B per stage = 36864
#define GST 3
#define GSMEM (GST * STG_BYTES)       // 110592 bytes

template<bool CVT_A, bool ROUND>
__device__ __forceinline__ void gemm_body(
    const float* __restrict__ A, const float* __restrict__ Bt, float* __restrict__ C)
{
    extern __shared__ __align__(1024) unsigned char sgm[];

    const int tid  = threadIdx.x;
    const int warp = tid >> 5;
    const int lane = tid & 31;
    const int l4   = lane >> 2;
    const int lm4  = lane & 3;
    const int wm0  = (warp >> 1) * 32;
    const int wn0  = (warp & 1) * 64;
    const int m0   = blockIdx.y * 128;
    const int n0   = blockIdx.x * 128;

    // LDSM per-lane address components
    const int arow = lane & 15;               // A-frag: rows of 16-row tile
    const int acol = (lane >> 4) * 4;         // k sub-col (0 or 4)
    const int brow = ((lane >> 4) << 3) + (lane & 7);  // B-frag pair rows
    const int bcol = ((lane >> 3) & 1) * 4;

    float acc[2][8][4];
    #pragma unroll
    for (int mi = 0; mi < 2; mi++)
        #pragma unroll
        for (int ni = 0; ni < 8; ni++)
            #pragma unroll
            for (int q = 0; q < 4; q++) acc[mi][ni][q] = 0.0f;

    const uint32_t sbase = s2u(sgm);

    auto load_stage = [&](int s, int k0) {
        uint32_t ab = sbase + s * STG_BYTES;
        uint32_t bb = ab + TILE_B;
        #pragma unroll
        for (int t = 0; t < 4; t++) {
            int id = tid + t * 256;          // 1024 ids
            int r = id >> 3;
            int c = (id & 7) * 4;
            CP16(ab + (r * TSTR + c) * 4, A  + (size_t)(m0 + r) * EMBD + k0 + c);
        }
        #pragma unroll
        for (int t = 0; t < 4; t++) {
            int id = tid + t * 256;
            int r = id >> 3;
            int c = (id & 7) * 4;
            CP16(bb + (r * TSTR + c) * 4, Bt + (size_t)(n0 + r) * EMBD + k0 + c);
        }
        CP_COMMIT();
    };

    load_stage(0, 0);
    load_stage(1, 32);

    const int KT = EMBD / 32;  // 32
    for (int kt = 0; kt < KT; kt++) {
        const int s = kt % GST;
        if (kt < KT - 1) { CP_WAIT(1); } else { CP_WAIT(0); }
        __syncthreads();
        if (kt + 2 < KT) load_stage((kt + 2) % GST, (kt + 2) * 32);

        const uint32_t ab = sbase + s * STG_BYTES;
        const uint32_t aoff = ab + ((wm0 + arow) * TSTR + acol) * 4;
        const uint32_t boff = ab + TILE_B + ((wn0 + brow) * TSTR + bcol) * 4;

        #pragma unroll
        for (int kk = 0; kk < 32; kk += 8) {
            unsigned a0[4], a1[4];
            LDSM4(a0, aoff + kk * 4);
            LDSM4(a1, aoff + 16 * TSTR * 4 + kk * 4);
            if (CVT_A) {
                #pragma unroll
                for (int q = 0; q < 4; q++) {
                    a0[q] = f2tf(__uint_as_float(a0[q]));
                    a1[q] = f2tf(__uint_as_float(a1[q]));
                }
            }
            unsigned bfr[4][4];
            #pragma unroll
            for (int p = 0; p < 4; p++)
                LDSM4(bfr[p], boff + p * 16 * TSTR * 4 + kk * 4);
            #pragma unroll
            for (int ni = 0; ni < 8; ni++) {
                const unsigned* bf = &bfr[ni >> 1][(ni & 1) * 2];
                mma8(acc[0][ni], a0, bf);
                mma8(acc[1][ni], a1, bf);
            }
        }
    }

    #pragma unroll
    for (int mi = 0; mi < 2; mi++) {
        #pragma unroll
        for (int ni = 0; ni < 8; ni++) {
            int row = m0 + wm0 + mi * 16 + l4;
            int col = n0 + wn0 + ni * 8 + lm4 * 2;
            float v0 = acc[mi][ni][0], v1 = acc[mi][ni][1];
            float v2 = acc[mi][ni][2], v3 = acc[mi][ni][3];
            if (ROUND) {
                v0 = __uint_as_float(f2tf(v0));
                v1 = __uint_as_float(f2tf(v1));
                v2 = __uint_as_float(f2tf(v2));
                v3 = __uint_as_float(f2tf(v3));
            }
            *(float2*)&C[(size_t)row * EMBD + col] = make_float2(v0, v1);
            *(float2*)&C[(size_t)(row + 8) * EMBD + col] = make_float2(v2, v3);
        }
    }
}

__global__ __launch_bounds__(256, 2) void gemm_qkv(
    const float* __restrict__ X, const float* __restrict__ Wt,
    float* __restrict__ C0, float* __restrict__ C1, float* __restrict__ C2)
{
    const float* Bt = Wt + (size_t)blockIdx.z * EMBD * EMBD;
    float* C = (blockIdx.z == 0) ? C0 : (blockIdx.z == 1) ? C1 : C2;
    gemm_body<true, true>(X, Bt, C);
}

__global__ __launch_bounds__(256, 2) void gemm_out(
    const float* __restrict__ A, const float* __restrict__ Wt, float* __restrict__ C)
{
    gemm_body<false, false>(A, Wt, C);
}

// ---------------------------------------------------------------------------
// Causal flash attention. One CTA = 128 q-rows of one (b,h), 256 threads.
// Q/K fragments via LDSM; V scalar; P via intra-quad shuffles (no P smem).
// ---------------------------------------------------------------------------
#define QST 68
#define KST 68
#define VST 72
#define KSZ (64 * KST)
#define VSZ (64 * VST)
#define ATTN_SMEM ((128*QST + 2*KSZ + 2*VSZ) * 4)  // 106496 bytes

__global__ __launch_bounds__(256, 2) void attn_flash(
    const float* __restrict__ Q, const float* __restrict__ K,
    const float* __restrict__ V, float* __restrict__ O)
{
    extern __shared__ __align__(1024) unsigned char sgm[];
    unsigned* sa = (unsigned*)sgm;
    unsigned* Qs = sa;
    unsigned* Ks = Qs + 128 * QST;
    unsigned* Vs = Ks + 2 * KSZ;

    const int tid  = threadIdx.x;
    const int warp = tid >> 5;
    const int lane = tid & 31;
    const int l4   = lane >> 2;
    const int lm4  = lane & 3;
    const int w16  = warp * 16;

    const int qb = (gridDim.x - 1) - blockIdx.x;   // longest blocks first
    const int q0 = qb * 128;
    const int bh = blockIdx.y;
    const int b  = bh >> 4;
    const int h  = bh & 15;
    const size_t headoff = (size_t)b * SEQ * EMBD + (size_t)h * HDIM;
    const float SCALE = 0.125f;

    const int src1 = (lane & 28) | (lm4 >> 1);
    const int src2 = src1 + 2;
    const bool par = (lm4 & 1);

    // LDSM address components
    const int arow = lane & 15;
    const int acol = (lane >> 4) * 4;
    const int brow = ((lane >> 4) << 3) + (lane & 7);
    const int bcol = ((lane >> 3) & 1) * 4;

    #pragma unroll
    for (int t = 0; t < 8; t++) {
        int idx = tid + t * 256;
        int r = idx >> 4;
        int c = (idx & 15) * 4;
        *(uint4*)&Qs[r * QST + c] =
            *(const uint4*)(Q + headoff + (size_t)(q0 + r) * EMBD + c);
    }

    auto load_kv = [&](int j, int s) {
        #pragma unroll
        for (int t = 0; t < 4; t++) {
            int idx = tid + t * 256;
            int r = idx >> 4;
            int c = (idx & 15) * 4;
            CP16(s2u(&Ks[s * KSZ + r * KST + c]),
                 K + headoff + (size_t)(j * 64 + r) * EMBD + c);
            CP16(s2u(&Vs[s * VSZ + r * VST + c]),
                 V + headoff + (size_t)(j * 64 + r) * EMBD + c);
        }
        CP_COMMIT();
    };

    float m0 = -INFINITY, m1 = -INFINITY, l0 = 0.0f, l1 = 0.0f;
    float o[8][4];
    #pragma unroll
    for (int ni = 0; ni < 8; ni++)
        #pragma unroll
        for (int q = 0; q < 4; q++) o[ni][q] = 0.0f;

    const int jmax = 2 * qb + 1;
    load_kv(0, 0);

    const uint32_t qoff = s2u(Qs) + ((w16 + arow) * QST + acol) * 4;

    for (int j = 0; j <= jmax; j++) {
        CP_WAIT(0);
        __syncthreads();
        if (j < jmax) load_kv(j + 1, (j + 1) & 1);

        const unsigned* Kst = &Ks[(j & 1) * KSZ];
        const unsigned* Vst = &Vs[(j & 1) * VSZ];
        const uint32_t koff = s2u(Kst) + (brow * KST + bcol) * 4;

        // S = Q K^T  (warp: 16 q-rows x 64 key-cols)
        float s[8][4];
        #pragma unroll
        for (int ni = 0; ni < 8; ni++)
            #pragma unroll
            for (int q = 0; q < 4; q++) s[ni][q] = 0.0f;

        #pragma unroll
        for (int kk = 0; kk < 64; kk += 8) {
            unsigned a[4];
            LDSM4(a, qoff + kk * 4);
            unsigned bfr[4][4];
            #pragma unroll
            for (int p = 0; p < 4; p++)
                LDSM4(bfr[p], koff + p * 16 * KST * 4 + kk * 4);
            #pragma unroll
            for (int ni = 0; ni < 8; ni++)
                mma8(s[ni], a, &bfr[ni >> 1][(ni & 1) * 2]);
        }

        const int grow0 = q0 + w16 + l4;
        const int grow1 = grow0 + 8;
        const bool pm = (j * 64 + 63) > (q0 + w16);
        float rm0 = -INFINITY, rm1 = -INFINITY;
        #pragma unroll
        for (int ni = 0; ni < 8; ni++) {
            int gc = j * 64 + ni * 8 + lm4 * 2;
            float v0 = s[ni][0] * SCALE;
            float v1 = s[ni][1] * SCALE;
            float v2 = s[ni][2] * SCALE;
            float v3 = s[ni][3] * SCALE;
            if (pm) {
                if (gc     > grow0) v0 = -INFINITY;
                if (gc + 1 > grow0) v1 = -INFINITY;
                if (gc     > grow1) v2 = -INFINITY;
                if (gc + 1 > grow1) v3 = -INFINITY;
            }
            s[ni][0] = v0; s[ni][1] = v1; s[ni][2] = v2; s[ni][3] = v3;
            rm0 = fmaxf(rm0, fmaxf(v0, v1));
            rm1 = fmaxf(rm1, fmaxf(v2, v3));
        }
        #pragma unroll
        for (int off = 1; off < 4; off <<= 1) {
            rm0 = fmaxf(rm0, __shfl_xor_sync(0xffffffffu, rm0, off));
            rm1 = fmaxf(rm1, __shfl_xor_sync(0xffffffffu, rm1, off));
        }

        float nm0 = fmaxf(m0, rm0);
        float nm1 = fmaxf(m1, rm1);
        float a0 = __expf(m0 - nm0);
        float a1 = __expf(m1 - nm1);
        m0 = nm0; m1 = nm1;

        float rs0 = 0.0f, rs1 = 0.0f;
        #pragma unroll
        for (int ni = 0; ni < 8; ni++) {
            float p0 = __expf(s[ni][0] - nm0);
            float p1 = __expf(s[ni][1] - nm0);
            float p2 = __expf(s[ni][2] - nm1);
            float p3 = __expf(s[ni][3] - nm1);
            rs0 += p0 + p1;
            rs1 += p2 + p3;
            s[ni][0] = p0; s[ni][1] = p1; s[ni][2] = p2; s[ni][3] = p3;
            o[ni][0] *= a0; o[ni][1] *= a0;
            o[ni][2] *= a1; o[ni][3] *= a1;
        }
        #pragma unroll
        for (int off = 1; off < 4; off <<= 1) {
            rs0 += __shfl_xor_sync(0xffffffffu, rs0, off);
            rs1 += __shfl_xor_sync(0xffffffffu, rs1, off);
        }
        l0 = a0 * l0 + rs0;
        l1 = a1 * l1 + rs1;

        // O += P @ V.  P fragments built from s[][] via intra-quad shuffles.
        #pragma unroll
        for (int kb = 0; kb < 8; kb++) {
            unsigned u0 = f2tf(s[kb][0]);
            unsigned u1 = f2tf(s[kb][1]);
            unsigned u2 = f2tf(s[kb][2]);
            unsigned u3 = f2tf(s[kb][3]);
            unsigned t0 = __shfl_sync(0xffffffffu, u0, src1);
            unsigned t1 = __shfl_sync(0xffffffffu, u1, src1);
            unsigned t2 = __shfl_sync(0xffffffffu, u2, src1);
            unsigned t3 = __shfl_sync(0xffffffffu, u3, src1);
            unsigned t4 = __shfl_sync(0xffffffffu, u0, src2);
            unsigned t5 = __shfl_sync(0xffffffffu, u1, src2);
            unsigned t6 = __shfl_sync(0xffffffffu, u2, src2);
            unsigned t7 = __shfl_sync(0xffffffffu, u3, src2);
            unsigned a[4];
            a[0] = par ? t1 : t0;
            a[1] = par ? t3 : t2;
            a[2] = par ? t5 : t4;
            a[3] = par ? t7 : t6;
            const int kk = kb * 8;
            #pragma unroll
            for (int ni = 0; ni < 8; ni++) {
                unsigned bf[2];
                bf[0] = Vst[(kk + lm4)     * VST + ni * 8 + l4];
                bf[1] = Vst[(kk + lm4 + 4) * VST + ni * 8 + l4];
                mma8(o[ni], a, bf);
            }
        }
    }

    float i0 = 1.0f / l0;
    float i1 = 1.0f / l1;
    #pragma unroll
    for (int ni = 0; ni < 8; ni++) {
        int gr = b * SEQ + q0 + w16 + l4;
        int gc = h * HDIM + ni * 8 + lm4 * 2;
        *(float2*)&O[(size_t)gr * EMBD + gc] = make_float2(
            __uint_as_float(f2tf(o[ni][0] * i0)),
            __uint_as_float(f2tf(o[ni][1] * i0)));
        *(float2*)&O[(size_t)(gr + 8) * EMBD + gc] = make_float2(
            __uint_as_float(f2tf(o[ni][2] * i1)),
            __uint_as_float(f2tf(o[ni][3] * i1)));
    }
}

// ---------------------------------------------------------------------------
// Launch
// ---------------------------------------------------------------------------
extern "C" void kernel_launch(void* const* d_in, const int* in_sizes, int n_in,
                              void* d_out, int out_size)
{
    const float* x  = (const float*)d_in[0];
    const float* Wq = (const float*)d_in[1];
    const float* Wk = (const float*)d_in[2];
    const float* Wv = (const float*)d_in[3];
    const float* Wo = (const float*)d_in[4];
    float* out = (float*)d_out;

    float *Qp, *Kp, *Vp, *Ap, *Wp;
    cudaGetSymbolAddress((void**)&Qp, g_Q);
    cudaGetSymbolAddress((void**)&Kp, g_K);
    cudaGetSymbolAddress((void**)&Vp, g_V);
    cudaGetSymbolAddress((void**)&Ap, g_A);
    cudaGetSymbolAddress((void**)&Wp, g_W);

    cudaFuncSetAttribute(gemm_qkv,   cudaFuncAttributeMaxDynamicSharedMemorySize, GSMEM);
    cudaFuncSetAttribute(gemm_out,   cudaFuncAttributeMaxDynamicSharedMemorySize, GSMEM);
    cudaFuncSetAttribute(attn_flash, cudaFuncAttributeMaxDynamicSharedMemorySize, ATTN_SMEM);

    dim3 gt(EMBD / 32, EMBD / 32, 4);   // (32, 32, 4)
    round_wt<<<gt, 256>>>(Wq, Wk, Wv, Wo, Wp);

    dim3 gqkv(EMBD / 128, MROWS / 128, 3);   // (8, 64, 3)
    gemm_qkv<<<gqkv, 256, GSMEM>>>(x, Wp, Qp, Kp, Vp);

    dim3 ga(SEQ / 128, BATCH * NHEAD);       // (16, 64)
    attn_flash<<<ga, 256, ATTN_SMEM>>>(Qp, Kp, Vp, Ap);

    dim3 go(EMBD / 128, MROWS / 128);        // (8, 64)
    gemm_out<<<go, 256, GSMEM>>>(Ap, Wp + 3 * (size_t)EMBD * EMBD, out);
}

// round 6
// speedup vs baseline: 2.0897x; 1.7160x over previous
#include <cuda_runtime.h>
#include <cuda_fp16.h>
#include <math.h>
#include <stdint.h>

// ---------------------------------------------------------------------------
// MultiHeadAttention: x@Wq/Wk/Wv -> causal flash attention -> @Wo
// B=4, S=2048, E=1024, H=16, Hs=64. fp32 I/O.
// R6: FP16 tensor-core math (same 10-bit mantissa as tf32; all values in
//     fp16 range). m16n8k16 HMMA = 2x FLOP/instr vs tf32 k8. fp16 operands
//     halve smem+gmem traffic (BK=64 per stage, half the barriers). P->A
//     fragment conversion is register packing (no shuffles). Base ISA only.
// ---------------------------------------------------------------------------

#define BATCH 4
#define SEQ   2048
#define EMBD  1024
#define NHEAD 16
#define HDIM  64
#define MROWS (BATCH*SEQ)   // 8192

__device__ __align__(256) __half g_Q[MROWS * EMBD];
__device__ __align__(256) __half g_K[MROWS * EMBD];
__device__ __align__(256) __half g_V[MROWS * EMBD];
__device__ __align__(256) __half g_A[MROWS * EMBD];
__device__ __align__(256) __half g_X[MROWS * EMBD];        // fp16 x
__device__ __align__(256) __half g_W[4 * EMBD * EMBD];     // fp16, transposed [n][k]

__device__ __forceinline__ uint32_t s2u(const void* p) {
    return (uint32_t)__cvta_generic_to_shared(p);
}
#define CP16(dst, src) \
    asm volatile("cp.async.cg.shared.global [%0], [%1], 16;\n" :: "r"(dst), "l"(src))
#define CP_COMMIT()  asm volatile("cp.async.commit_group;\n" ::: "memory")
#define CP_WAIT(n)   asm volatile("cp.async.wait_group %0;\n" :: "n"(n) : "memory")

#define LDSM4(r, addr) \
    asm volatile("ldmatrix.sync.aligned.m8n8.x4.shared.b16 {%0,%1,%2,%3}, [%4];" \
        : "=r"((r)[0]), "=r"((r)[1]), "=r"((r)[2]), "=r"((r)[3]) : "r"(addr))
#define LDSM4T(r, addr) \
    asm volatile("ldmatrix.sync.aligned.m8n8.x4.trans.shared.b16 {%0,%1,%2,%3}, [%4];" \
        : "=r"((r)[0]), "=r"((r)[1]), "=r"((r)[2]), "=r"((r)[3]) : "r"(addr))

// fp16 MMA, fp32 accumulate: D(16x8) += A(16x16) * B(16x8)
__device__ __forceinline__ void mma16(float* c, const unsigned* a, const unsigned* b) {
    asm volatile(
        "mma.sync.aligned.m16n8k16.row.col.f32.f16.f16.f32 "
        "{%0,%1,%2,%3}, {%4,%5,%6,%7}, {%8,%9}, {%0,%1,%2,%3};\n"
        : "+f"(c[0]), "+f"(c[1]), "+f"(c[2]), "+f"(c[3])
        : "r"(a[0]), "r"(a[1]), "r"(a[2]), "r"(a[3]),
          "r"(b[0]), "r"(b[1]));
}

__device__ __forceinline__ unsigned pack_h2(float lo, float hi) {
    __half2 h = __floats2half2_rn(lo, hi);
    return *(unsigned*)&h;
}

// ---------------------------------------------------------------------------
// Pre-passes: x -> fp16; weights -> fp16 transposed [n][k]
// ---------------------------------------------------------------------------
__global__ __launch_bounds__(256) void x2h(
    const float4* __restrict__ in, uint2* __restrict__ out, int n4)
{
    int i = blockIdx.x * 256 + threadIdx.x;
    if (i < n4) {
        float4 v = in[i];
        out[i] = make_uint2(pack_h2(v.x, v.y), pack_h2(v.z, v.w));
    }
}

__global__ __launch_bounds__(256) void round_wt(
    const float* __restrict__ w0, const float* __restrict__ w1,
    const float* __restrict__ w2, const float* __restrict__ w3,
    __half* __restrict__ out)
{
    __shared__ float t[32][33];
    const float* in = (blockIdx.z == 0) ? w0 : (blockIdx.z == 1) ? w1
                    : (blockIdx.z == 2) ? w2 : w3;
    __half* o = out + (size_t)blockIdx.z * EMBD * EMBD;
    int bx = blockIdx.x * 32, by = blockIdx.y * 32;
    int tx = threadIdx.x & 31, ty = threadIdx.x >> 5;   // 32x8
    #pragma unroll
    for (int i = 0; i < 32; i += 8)
        t[ty + i][tx] = in[(size_t)(by + ty + i) * EMBD + bx + tx];
    __syncthreads();
    #pragma unroll
    for (int i = 0; i < 32; i += 8)
        o[(size_t)(bx + ty + i) * EMBD + by + tx] = __float2half_rn(t[tx][ty + i]);
}

// ---------------------------------------------------------------------------
// FP16 GEMM: C[8192,1024] = A[m][k] @ Bt[n][k]^T. CTA tile 128x128, BK=64.
// fp16 tiles K-major, row = 128B data + 16B pad (144B, LDSM conflict-free).
// 256 threads = 8 warps (4m x 2n, warp 32x64), 3-stage cp.async.
// ---------------------------------------------------------------------------
#define RSTR 144                       // bytes per tile row
#define TILE_B (128 * RSTR)            // 18432
#define STG_BYTES (2 * TILE_B)         // 36864
#define GST 3
#define GSMEM (GST * STG_BYTES)        // 110592

template<bool HALF_OUT>
__device__ __forceinline__ void gemm_body(
    const __half* __restrict__ A, const __half* __restrict__ Bt, void* __restrict__ Cv)
{
    extern __shared__ __align__(1024) unsigned char sgm[];

    const int tid  = threadIdx.x;
    const int warp = tid >> 5;
    const int lane = tid & 31;
    const int l4   = lane >> 2;
    const int lm4  = lane & 3;
    const int wm0  = (warp >> 1) * 32;
    const int wn0  = (warp & 1) * 64;
    const int m0   = blockIdx.y * 128;
    const int n0   = blockIdx.x * 128;

    const int lrow = lane & 15;
    const int lcol = (lane >> 4) * 16;   // byte offset within row

    float acc[2][8][4];
    #pragma unroll
    for (int mi = 0; mi < 2; mi++)
        #pragma unroll
        for (int ni = 0; ni < 8; ni++)
            #pragma unroll
            for (int q = 0; q < 4; q++) acc[mi][ni][q] = 0.0f;

    const uint32_t sbase = s2u(sgm);

    auto load_stage = [&](int s, int k0) {   // k0 in halves
        uint32_t ab = sbase + s * STG_BYTES;
        uint32_t bb = ab + TILE_B;
        #pragma unroll
        for (int t = 0; t < 4; t++) {
            int id = tid + t * 256;          // 1024: 128 rows x 8 chunks
            int r = id >> 3;
            int c = (id & 7) * 8;            // halves
            CP16(ab + r * RSTR + c * 2, A  + (size_t)(m0 + r) * EMBD + k0 + c);
        }
        #pragma unroll
        for (int t = 0; t < 4; t++) {
            int id = tid + t * 256;
            int r = id >> 3;
            int c = (id & 7) * 8;
            CP16(bb + r * RSTR + c * 2, Bt + (size_t)(n0 + r) * EMBD + k0 + c);
        }
        CP_COMMIT();
    };

    load_stage(0, 0);
    load_stage(1, 64);

    const int KT = EMBD / 64;  // 16
    for (int kt = 0; kt < KT; kt++) {
        const int s = kt % GST;
        if (kt < KT - 1) { CP_WAIT(1); } else { CP_WAIT(0); }
        __syncthreads();
        if (kt + 2 < KT) load_stage((kt + 2) % GST, (kt + 2) * 64);

        const uint32_t ab   = sbase + s * STG_BYTES;
        const uint32_t aoff = ab + (wm0 + lrow) * RSTR + lcol;
        const uint32_t boff = ab + TILE_B + (wn0 + lrow) * RSTR + lcol;

        #pragma unroll
        for (int kk = 0; kk < 4; kk++) {      // 4 x k16
            unsigned a0[4], a1[4];
            LDSM4(a0, aoff + kk * 32);
            LDSM4(a1, aoff + 16 * RSTR + kk * 32);
            unsigned bf[4][4];
            #pragma unroll
            for (int ng = 0; ng < 4; ng++)
                LDSM4(bf[ng], boff + ng * 16 * RSTR + kk * 32);
            #pragma unroll
            for (int ni = 0; ni < 8; ni++) {
                unsigned b2[2] = { bf[ni >> 1][ni & 1], bf[ni >> 1][(ni & 1) + 2] };
                mma16(acc[0][ni], a0, b2);
                mma16(acc[1][ni], a1, b2);
            }
        }
    }

    #pragma unroll
    for (int mi = 0; mi < 2; mi++) {
        #pragma unroll
        for (int ni = 0; ni < 8; ni++) {
            int row = m0 + wm0 + mi * 16 + l4;
            int col = n0 + wn0 + ni * 8 + lm4 * 2;
            if (HALF_OUT) {
                __half* C = (__half*)Cv;
                *(unsigned*)&C[(size_t)row * EMBD + col] =
                    pack_h2(acc[mi][ni][0], acc[mi][ni][1]);
                *(unsigned*)&C[(size_t)(row + 8) * EMBD + col] =
                    pack_h2(acc[mi][ni][2], acc[mi][ni][3]);
            } else {
                float* C = (float*)Cv;
                *(float2*)&C[(size_t)row * EMBD + col] =
                    make_float2(acc[mi][ni][0], acc[mi][ni][1]);
                *(float2*)&C[(size_t)(row + 8) * EMBD + col] =
                    make_float2(acc[mi][ni][2], acc[mi][ni][3]);
            }
        }
    }
}

__global__ __launch_bounds__(256, 2) void gemm_qkv(
    const __half* __restrict__ X, const __half* __restrict__ Wt,
    __half* __restrict__ C0, __half* __restrict__ C1, __half* __restrict__ C2)
{
    const __half* Bt = Wt + (size_t)blockIdx.z * EMBD * EMBD;
    __half* C = (blockIdx.z == 0) ? C0 : (blockIdx.z == 1) ? C1 : C2;
    gemm_body<true>(X, Bt, C);
}

__global__ __launch_bounds__(256, 2) void gemm_out(
    const __half* __restrict__ A, const __half* __restrict__ Wt, float* __restrict__ C)
{
    gemm_body<false>(A, Wt, C);
}

// ---------------------------------------------------------------------------
// Causal flash attention (fp16 operands, fp32 softmax/accum).
// One CTA = 128 q-rows of one (b,h), 256 threads = 8 warps (16 q-rows each).
// K via LDSM (non-trans), V via LDSM.trans, P packed from S fragments.
// ---------------------------------------------------------------------------
#define QTB (128 * RSTR)               // 18432
#define KTB (64 * RSTR)                // 9216
#define ATTN_SMEM (QTB + 4 * KTB)      // 55296

__global__ __launch_bounds__(256, 2) void attn_flash(
    const __half* __restrict__ Q, const __half* __restrict__ K,
    const __half* __restrict__ V, __half* __restrict__ O)
{
    extern __shared__ __align__(1024) unsigned char sgm[];
    const uint32_t qbase = s2u(sgm);
    const uint32_t kbase = qbase + QTB;
    const uint32_t vbase = kbase + 2 * KTB;

    const int tid  = threadIdx.x;
    const int warp = tid >> 5;
    const int lane = tid & 31;
    const int l4   = lane >> 2;
    const int lm4  = lane & 3;
    const int w16  = warp * 16;

    const int lrow = lane & 15;
    const int lcol = (lane >> 4) * 16;

    const int qb = (gridDim.x - 1) - blockIdx.x;   // longest blocks first
    const int q0 = qb * 128;
    const int bh = blockIdx.y;
    const int b  = bh >> 4;
    const int h  = bh & 15;
    const size_t headoff = (size_t)b * SEQ * EMBD + (size_t)h * HDIM;
    const float SCALE = 0.125f;   // 1/sqrt(64)

    // Load Q tile (128 x 64 fp16) direct
    #pragma unroll
    for (int t = 0; t < 4; t++) {
        int idx = tid + t * 256;         // 1024: 128 rows x 8 chunks
        int r = idx >> 3;
        int c = (idx & 7) * 8;
        *(uint4*)(sgm + r * RSTR + c * 2) =
            *(const uint4*)(Q + headoff + (size_t)(q0 + r) * EMBD + c);
    }

    auto load_kv = [&](int j, int s) {
        #pragma unroll
        for (int t = 0; t < 2; t++) {
            int id = tid + t * 256;      // 512: 64 rows x 8 chunks
            int r = id >> 3;
            int c = (id & 7) * 8;
            CP16(kbase + s * KTB + r * RSTR + c * 2,
                 K + headoff + (size_t)(j * 64 + r) * EMBD + c);
        }
        #pragma unroll
        for (int t = 0; t < 2; t++) {
            int id = tid + t * 256;
            int r = id >> 3;
            int c = (id & 7) * 8;
            CP16(vbase + s * KTB + r * RSTR + c * 2,
                 V + headoff + (size_t)(j * 64 + r) * EMBD + c);
        }
        CP_COMMIT();
    };

    float m0 = -INFINITY, m1 = -INFINITY, l0 = 0.0f, l1 = 0.0f;
    float o[8][4];
    #pragma unroll
    for (int ni = 0; ni < 8; ni++)
        #pragma unroll
        for (int q = 0; q < 4; q++) o[ni][q] = 0.0f;

    const int jmax = 2 * qb + 1;
    load_kv(0, 0);

    const uint32_t qoff = qbase + (w16 + lrow) * RSTR + lcol;

    for (int j = 0; j <= jmax; j++) {
        CP_WAIT(0);
        __syncthreads();
        if (j < jmax) load_kv(j + 1, (j + 1) & 1);

        const uint32_t koff = kbase + (j & 1) * KTB + lrow * RSTR + lcol;
        const uint32_t voff = vbase + (j & 1) * KTB + lrow * RSTR + lcol;

        // S = Q K^T  (warp: 16 q-rows x 64 key-cols), 4 x k16 steps
        float s[8][4];
        #pragma unroll
        for (int ni = 0; ni < 8; ni++)
            #pragma unroll
            for (int q = 0; q < 4; q++) s[ni][q] = 0.0f;

        #pragma unroll
        for (int kk = 0; kk < 4; kk++) {
            unsigned a[4];
            LDSM4(a, qoff + kk * 32);
            unsigned bf[4][4];
            #pragma unroll
            for (int ng = 0; ng < 4; ng++)
                LDSM4(bf[ng], koff + ng * 16 * RSTR + kk * 32);
            #pragma unroll
            for (int ni = 0; ni < 8; ni++) {
                unsigned b2[2] = { bf[ni >> 1][ni & 1], bf[ni >> 1][(ni & 1) + 2] };
                mma16(s[ni], a, b2);
            }
        }

        // Scale + causal mask + online softmax (fp32)
        const int grow0 = q0 + w16 + l4;
        const int grow1 = grow0 + 8;
        const bool pm = (j * 64 + 63) > (q0 + w16);
        float rm0 = -INFINITY, rm1 = -INFINITY;
        #pragma unroll
        for (int ni = 0; ni < 8; ni++) {
            int gc = j * 64 + ni * 8 + lm4 * 2;
            float v0 = s[ni][0] * SCALE;
            float v1 = s[ni][1] * SCALE;
            float v2 = s[ni][2] * SCALE;
            float v3 = s[ni][3] * SCALE;
            if (pm) {
                if (gc     > grow0) v0 = -INFINITY;
                if (gc + 1 > grow0) v1 = -INFINITY;
                if (gc     > grow1) v2 = -INFINITY;
                if (gc + 1 > grow1) v3 = -INFINITY;
            }
            s[ni][0] = v0; s[ni][1] = v1; s[ni][2] = v2; s[ni][3] = v3;
            rm0 = fmaxf(rm0, fmaxf(v0, v1));
            rm1 = fmaxf(rm1, fmaxf(v2, v3));
        }
        #pragma unroll
        for (int off = 1; off < 4; off <<= 1) {
            rm0 = fmaxf(rm0, __shfl_xor_sync(0xffffffffu, rm0, off));
            rm1 = fmaxf(rm1, __shfl_xor_sync(0xffffffffu, rm1, off));
        }

        float nm0 = fmaxf(m0, rm0);
        float nm1 = fmaxf(m1, rm1);
        float a0 = __expf(m0 - nm0);
        float a1 = __expf(m1 - nm1);
        m0 = nm0; m1 = nm1;

        float rs0 = 0.0f, rs1 = 0.0f;
        #pragma unroll
        for (int ni = 0; ni < 8; ni++) {
            float p0 = __expf(s[ni][0] - nm0);
            float p1 = __expf(s[ni][1] - nm0);
            float p2 = __expf(s[ni][2] - nm1);
            float p3 = __expf(s[ni][3] - nm1);
            rs0 += p0 + p1;
            rs1 += p2 + p3;
            s[ni][0] = p0; s[ni][1] = p1; s[ni][2] = p2; s[ni][3] = p3;
            o[ni][0] *= a0; o[ni][1] *= a0;
            o[ni][2] *= a1; o[ni][3] *= a1;
        }
        #pragma unroll
        for (int off = 1; off < 4; off <<= 1) {
            rs0 += __shfl_xor_sync(0xffffffffu, rs0, off);
            rs1 += __shfl_xor_sync(0xffffffffu, rs1, off);
        }
        l0 = a0 * l0 + rs0;
        l1 = a1 * l1 + rs1;

        // O += P @ V.  P A-fragments = packed S C-fragments (no shuffles).
        #pragma unroll
        for (int g = 0; g < 4; g++) {          // 4 x k16 key groups
            unsigned ap[4];
            ap[0] = pack_h2(s[2*g][0],   s[2*g][1]);
            ap[1] = pack_h2(s[2*g][2],   s[2*g][3]);
            ap[2] = pack_h2(s[2*g+1][0], s[2*g+1][1]);
            ap[3] = pack_h2(s[2*g+1][2], s[2*g+1][3]);
            #pragma unroll
            for (int dg = 0; dg < 4; dg++) {   // 4 x 16 dims
                unsigned vf[4];
                LDSM4T(vf, voff + (g * 16 - lrow) * RSTR + lrow * RSTR + dg * 32);
                unsigned b0[2] = { vf[0], vf[1] };
                unsigned b1[2] = { vf[2], vf[3] };
                mma16(o[2*dg],     ap, b0);
                mma16(o[2*dg + 1], ap, b1);
            }
        }
    }

    // Epilogue: normalize, convert fp16, store to [B*S, EMBD] at head offset
    float i0 = 1.0f / l0;
    float i1 = 1.0f / l1;
    #pragma unroll
    for (int ni = 0; ni < 8; ni++) {
        int gr = b * SEQ + q0 + w16 + l4;
        int gc = h * HDIM + ni * 8 + lm4 * 2;
        *(unsigned*)&O[(size_t)gr * EMBD + gc] =
            pack_h2(o[ni][0] * i0, o[ni][1] * i0);
        *(unsigned*)&O[(size_t)(gr + 8) * EMBD + gc] =
            pack_h2(o[ni][2] * i1, o[ni][3] * i1);
    }
}

// ---------------------------------------------------------------------------
// Launch
// ---------------------------------------------------------------------------
extern "C" void kernel_launch(void* const* d_in, const int* in_sizes, int n_in,
                              void* d_out, int out_size)
{
    const float* x  = (const float*)d_in[0];
    const float* Wq = (const float*)d_in[1];
    const float* Wk = (const float*)d_in[2];
    const float* Wv = (const float*)d_in[3];
    const float* Wo = (const float*)d_in[4];
    float* out = (float*)d_out;

    __half *Qp, *Kp, *Vp, *Ap, *Xp, *Wp;
    cudaGetSymbolAddress((void**)&Qp, g_Q);
    cudaGetSymbolAddress((void**)&Kp, g_K);
    cudaGetSymbolAddress((void**)&Vp, g_V);
    cudaGetSymbolAddress((void**)&Ap, g_A);
    cudaGetSymbolAddress((void**)&Xp, g_X);
    cudaGetSymbolAddress((void**)&Wp, g_W);

    cudaFuncSetAttribute(gemm_qkv,   cudaFuncAttributeMaxDynamicSharedMemorySize, GSMEM);
    cudaFuncSetAttribute(gemm_out,   cudaFuncAttributeMaxDynamicSharedMemorySize, GSMEM);
    cudaFuncSetAttribute(attn_flash, cudaFuncAttributeMaxDynamicSharedMemorySize, ATTN_SMEM);

    const int XN4 = MROWS * EMBD / 4;   // 2097152
    x2h<<<XN4 / 256, 256>>>((const float4*)x, (uint2*)Xp, XN4);

    dim3 gt(EMBD / 32, EMBD / 32, 4);   // (32, 32, 4)
    round_wt<<<gt, 256>>>(Wq, Wk, Wv, Wo, Wp);

    dim3 gqkv(EMBD / 128, MROWS / 128, 3);   // (8, 64, 3)
    gemm_qkv<<<gqkv, 256, GSMEM>>>(Xp, Wp, Qp, Kp, Vp);

    dim3 ga(SEQ / 128, BATCH * NHEAD);       // (16, 64)
    attn_flash<<<ga, 256, ATTN_SMEM>>>(Qp, Kp, Vp, Ap);

    dim3 go(EMBD / 128, MROWS / 128);        // (8, 64)
    gemm_out<<<go, 256, GSMEM>>>(Ap, Wp + 3 * (size_t)EMBD * EMBD, out);
}

// round 7
// speedup vs baseline: 2.1888x; 1.0474x over previous
#include <cuda_runtime.h>
#include <cuda_fp16.h>
#include <math.h>
#include <stdint.h>

// ---------------------------------------------------------------------------
// MultiHeadAttention: x@Wq/Wk/Wv -> causal flash attention -> @Wo
// B=4, S=2048, E=1024, H=16, Hs=64. fp32 I/O, FP16 tensor-core math.
// R7: softmax de-bloat. Q pre-scaled by 0.125*log2e in GEMM epilogue ->
//     bare ex2.approx.f32; row-sum via all-ones MMA column; warp-uniform
//     skip of fully-masked tiles; vote-guarded O/l rescale.
// ---------------------------------------------------------------------------

#define BATCH 4
#define SEQ   2048
#define EMBD  1024
#define NHEAD 16
#define HDIM  64
#define MROWS (BATCH*SEQ)   // 8192

#define QSCALE 0.18033688011112042f   // 0.125 * log2(e)

__device__ __align__(256) __half g_Q[MROWS * EMBD];
__device__ __align__(256) __half g_K[MROWS * EMBD];
__device__ __align__(256) __half g_V[MROWS * EMBD];
__device__ __align__(256) __half g_A[MROWS * EMBD];
__device__ __align__(256) __half g_X[MROWS * EMBD];
__device__ __align__(256) __half g_W[4 * EMBD * EMBD];   // fp16, transposed [n][k]

__device__ __forceinline__ uint32_t s2u(const void* p) {
    return (uint32_t)__cvta_generic_to_shared(p);
}
#define CP16(dst, src) \
    asm volatile("cp.async.cg.shared.global [%0], [%1], 16;\n" :: "r"(dst), "l"(src))
#define CP_COMMIT()  asm volatile("cp.async.commit_group;\n" ::: "memory")
#define CP_WAIT(n)   asm volatile("cp.async.wait_group %0;\n" :: "n"(n) : "memory")

#define LDSM4(r, addr) \
    asm volatile("ldmatrix.sync.aligned.m8n8.x4.shared.b16 {%0,%1,%2,%3}, [%4];" \
        : "=r"((r)[0]), "=r"((r)[1]), "=r"((r)[2]), "=r"((r)[3]) : "r"(addr))
#define LDSM4T(r, addr) \
    asm volatile("ldmatrix.sync.aligned.m8n8.x4.trans.shared.b16 {%0,%1,%2,%3}, [%4];" \
        : "=r"((r)[0]), "=r"((r)[1]), "=r"((r)[2]), "=r"((r)[3]) : "r"(addr))

__device__ __forceinline__ void mma16(float* c, const unsigned* a, const unsigned* b) {
    asm volatile(
        "mma.sync.aligned.m16n8k16.row.col.f32.f16.f16.f32 "
        "{%0,%1,%2,%3}, {%4,%5,%6,%7}, {%8,%9}, {%0,%1,%2,%3};\n"
        : "+f"(c[0]), "+f"(c[1]), "+f"(c[2]), "+f"(c[3])
        : "r"(a[0]), "r"(a[1]), "r"(a[2]), "r"(a[3]),
          "r"(b[0]), "r"(b[1]));
}

__device__ __forceinline__ unsigned pack_h2(float lo, float hi) {
    __half2 h = __floats2half2_rn(lo, hi);
    return *(unsigned*)&h;
}

__device__ __forceinline__ float ex2f(float x) {
    float y;
    asm("ex2.approx.f32 %0, %1;" : "=f"(y) : "f"(x));
    return y;
}

// ---------------------------------------------------------------------------
// Pre-passes
// ---------------------------------------------------------------------------
__global__ __launch_bounds__(256) void x2h(
    const float4* __restrict__ in, uint2* __restrict__ out, int n4)
{
    int i = blockIdx.x * 256 + threadIdx.x;
    if (i < n4) {
        float4 v = in[i];
        out[i] = make_uint2(pack_h2(v.x, v.y), pack_h2(v.z, v.w));
    }
}

__global__ __launch_bounds__(256) void round_wt(
    const float* __restrict__ w0, const float* __restrict__ w1,
    const float* __restrict__ w2, const float* __restrict__ w3,
    __half* __restrict__ out)
{
    __shared__ float t[32][33];
    const float* in = (blockIdx.z == 0) ? w0 : (blockIdx.z == 1) ? w1
                    : (blockIdx.z == 2) ? w2 : w3;
    __half* o = out + (size_t)blockIdx.z * EMBD * EMBD;
    int bx = blockIdx.x * 32, by = blockIdx.y * 32;
    int tx = threadIdx.x & 31, ty = threadIdx.x >> 5;
    #pragma unroll
    for (int i = 0; i < 32; i += 8)
        t[ty + i][tx] = in[(size_t)(by + ty + i) * EMBD + bx + tx];
    __syncthreads();
    #pragma unroll
    for (int i = 0; i < 32; i += 8)
        o[(size_t)(bx + ty + i) * EMBD + by + tx] = __float2half_rn(t[tx][ty + i]);
}

// ---------------------------------------------------------------------------
// FP16 GEMM: C[8192,1024] = A[m][k] @ Bt[n][k]^T. CTA 128x128, BK=64,
// 3-stage cp.async, LDSM fragments. oscale applied to fp16 outputs.
// ---------------------------------------------------------------------------
#define RSTR 144
#define TILE_B (128 * RSTR)
#define STG_BYTES (2 * TILE_B)
#define GST 3
#define GSMEM (GST * STG_BYTES)        // 110592

template<bool HALF_OUT>
__device__ __forceinline__ void gemm_body(
    const __half* __restrict__ A, const __half* __restrict__ Bt, void* __restrict__ Cv,
    float oscale)
{
    extern __shared__ __align__(1024) unsigned char sgm[];

    const int tid  = threadIdx.x;
    const int warp = tid >> 5;
    const int lane = tid & 31;
    const int l4   = lane >> 2;
    const int lm4  = lane & 3;
    const int wm0  = (warp >> 1) * 32;
    const int wn0  = (warp & 1) * 64;
    const int m0   = blockIdx.y * 128;
    const int n0   = blockIdx.x * 128;

    const int lrow = lane & 15;
    const int lcol = (lane >> 4) * 16;

    float acc[2][8][4];
    #pragma unroll
    for (int mi = 0; mi < 2; mi++)
        #pragma unroll
        for (int ni = 0; ni < 8; ni++)
            #pragma unroll
            for (int q = 0; q < 4; q++) acc[mi][ni][q] = 0.0f;

    const uint32_t sbase = s2u(sgm);

    auto load_stage = [&](int s, int k0) {
        uint32_t ab = sbase + s * STG_BYTES;
        uint32_t bb = ab + TILE_B;
        #pragma unroll
        for (int t = 0; t < 4; t++) {
            int id = tid + t * 256;
            int r = id >> 3;
            int c = (id & 7) * 8;
            CP16(ab + r * RSTR + c * 2, A  + (size_t)(m0 + r) * EMBD + k0 + c);
        }
        #pragma unroll
        for (int t = 0; t < 4; t++) {
            int id = tid + t * 256;
            int r = id >> 3;
            int c = (id & 7) * 8;
            CP16(bb + r * RSTR + c * 2, Bt + (size_t)(n0 + r) * EMBD + k0 + c);
        }
        CP_COMMIT();
    };

    load_stage(0, 0);
    load_stage(1, 64);

    const int KT = EMBD / 64;  // 16
    for (int kt = 0; kt < KT; kt++) {
        const int s = kt % GST;
        if (kt < KT - 1) { CP_WAIT(1); } else { CP_WAIT(0); }
        __syncthreads();
        if (kt + 2 < KT) load_stage((kt + 2) % GST, (kt + 2) * 64);

        const uint32_t ab   = sbase + s * STG_BYTES;
        const uint32_t aoff = ab + (wm0 + lrow) * RSTR + lcol;
        const uint32_t boff = ab + TILE_B + (wn0 + lrow) * RSTR + lcol;

        #pragma unroll
        for (int kk = 0; kk < 4; kk++) {
            unsigned a0[4], a1[4];
            LDSM4(a0, aoff + kk * 32);
            LDSM4(a1, aoff + 16 * RSTR + kk * 32);
            unsigned bf[4][4];
            #pragma unroll
            for (int ng = 0; ng < 4; ng++)
                LDSM4(bf[ng], boff + ng * 16 * RSTR + kk * 32);
            #pragma unroll
            for (int ni = 0; ni < 8; ni++) {
                unsigned b2[2] = { bf[ni >> 1][ni & 1], bf[ni >> 1][(ni & 1) + 2] };
                mma16(acc[0][ni], a0, b2);
                mma16(acc[1][ni], a1, b2);
            }
        }
    }

    #pragma unroll
    for (int mi = 0; mi < 2; mi++) {
        #pragma unroll
        for (int ni = 0; ni < 8; ni++) {
            int row = m0 + wm0 + mi * 16 + l4;
            int col = n0 + wn0 + ni * 8 + lm4 * 2;
            if (HALF_OUT) {
                __half* C = (__half*)Cv;
                *(unsigned*)&C[(size_t)row * EMBD + col] =
                    pack_h2(acc[mi][ni][0] * oscale, acc[mi][ni][1] * oscale);
                *(unsigned*)&C[(size_t)(row + 8) * EMBD + col] =
                    pack_h2(acc[mi][ni][2] * oscale, acc[mi][ni][3] * oscale);
            } else {
                float* C = (float*)Cv;
                *(float2*)&C[(size_t)row * EMBD + col] =
                    make_float2(acc[mi][ni][0], acc[mi][ni][1]);
                *(float2*)&C[(size_t)(row + 8) * EMBD + col] =
                    make_float2(acc[mi][ni][2], acc[mi][ni][3]);
            }
        }
    }
}

__global__ __launch_bounds__(256, 2) void gemm_qkv(
    const __half* __restrict__ X, const __half* __restrict__ Wt,
    __half* __restrict__ C0, __half* __restrict__ C1, __half* __restrict__ C2)
{
    const __half* Bt = Wt + (size_t)blockIdx.z * EMBD * EMBD;
    __half* C = (blockIdx.z == 0) ? C0 : (blockIdx.z == 1) ? C1 : C2;
    float sc = (blockIdx.z == 0) ? QSCALE : 1.0f;   // fold 0.125*log2e into Q
    gemm_body<true>(X, Bt, C, sc);
}

__global__ __launch_bounds__(256, 2) void gemm_out(
    const __half* __restrict__ A, const __half* __restrict__ Wt, float* __restrict__ C)
{
    gemm_body<false>(A, Wt, C, 1.0f);
}

// ---------------------------------------------------------------------------
// Causal flash attention. One CTA = 128 q-rows of one (b,h), 256 threads.
// Scores arrive in log2 units (Q pre-scaled). l accumulated via ones-MMA.
// ---------------------------------------------------------------------------
#define QTB (128 * RSTR)
#define KTB (64 * RSTR)
#define ATTN_SMEM (QTB + 4 * KTB)      // 55296

__global__ __launch_bounds__(256, 2) void attn_flash(
    const __half* __restrict__ Q, const __half* __restrict__ K,
    const __half* __restrict__ V, __half* __restrict__ O)
{
    extern __shared__ __align__(1024) unsigned char sgm[];
    const uint32_t qbase = s2u(sgm);
    const uint32_t kbase = qbase + QTB;
    const uint32_t vbase = kbase + 2 * KTB;

    const int tid  = threadIdx.x;
    const int warp = tid >> 5;
    const int lane = tid & 31;
    const int l4   = lane >> 2;
    const int lm4  = lane & 3;
    const int w16  = warp * 16;

    const int lrow = lane & 15;
    const int lcol = (lane >> 4) * 16;

    const int qb = (gridDim.x - 1) - blockIdx.x;   // longest blocks first
    const int q0 = qb * 128;
    const int bh = blockIdx.y;
    const int b  = bh >> 4;
    const int h  = bh & 15;
    const size_t headoff = (size_t)b * SEQ * EMBD + (size_t)h * HDIM;

    const unsigned ONESH2 = 0x3C003C00u;   // half2(1,1)

    // Load Q tile (128 x 64 fp16) direct
    #pragma unroll
    for (int t = 0; t < 4; t++) {
        int idx = tid + t * 256;
        int r = idx >> 3;
        int c = (idx & 7) * 8;
        *(uint4*)(sgm + r * RSTR + c * 2) =
            *(const uint4*)(Q + headoff + (size_t)(q0 + r) * EMBD + c);
    }

    auto load_kv = [&](int j, int s) {
        #pragma unroll
        for (int t = 0; t < 2; t++) {
            int id = tid + t * 256;
            int r = id >> 3;
            int c = (id & 7) * 8;
            CP16(kbase + s * KTB + r * RSTR + c * 2,
                 K + headoff + (size_t)(j * 64 + r) * EMBD + c);
        }
        #pragma unroll
        for (int t = 0; t < 2; t++) {
            int id = tid + t * 256;
            int r = id >> 3;
            int c = (id & 7) * 8;
            CP16(vbase + s * KTB + r * RSTR + c * 2,
                 V + headoff + (size_t)(j * 64 + r) * EMBD + c);
        }
        CP_COMMIT();
    };

    float m0 = -INFINITY, m1 = -INFINITY;
    float o[8][4];
    float lacc[4];
    #pragma unroll
    for (int ni = 0; ni < 8; ni++)
        #pragma unroll
        for (int q = 0; q < 4; q++) o[ni][q] = 0.0f;
    #pragma unroll
    for (int q = 0; q < 4; q++) lacc[q] = 0.0f;

    const int jmax = 2 * qb + 1;
    load_kv(0, 0);

    const uint32_t qoff = qbase + (w16 + lrow) * RSTR + lcol;
    const int grow0 = q0 + w16 + l4;
    const int grow1 = grow0 + 8;

    for (int j = 0; j <= jmax; j++) {
        CP_WAIT(0);
        __syncthreads();
        if (j < jmax) load_kv(j + 1, (j + 1) & 1);

        // Fully-masked tile for this warp? (first key col > last q row)
        if (j * 64 > q0 + w16 + 15) continue;

        const uint32_t koff = kbase + (j & 1) * KTB + lrow * RSTR + lcol;
        const uint32_t voff = vbase + (j & 1) * KTB + lrow * RSTR + lcol;

        // S = Q K^T  (log2-units; warp: 16 q-rows x 64 key-cols)
        float s[8][4];
        #pragma unroll
        for (int ni = 0; ni < 8; ni++)
            #pragma unroll
            for (int q = 0; q < 4; q++) s[ni][q] = 0.0f;

        #pragma unroll
        for (int kk = 0; kk < 4; kk++) {
            unsigned a[4];
            LDSM4(a, qoff + kk * 32);
            unsigned bf[4][4];
            #pragma unroll
            for (int ng = 0; ng < 4; ng++)
                LDSM4(bf[ng], koff + ng * 16 * RSTR + kk * 32);
            #pragma unroll
            for (int ni = 0; ni < 8; ni++) {
                unsigned b2[2] = { bf[ni >> 1][ni & 1], bf[ni >> 1][(ni & 1) + 2] };
                mma16(s[ni], a, b2);
            }
        }

        // Causal mask (diag tiles only; warp-uniform branch)
        if (j * 64 + 63 > q0 + w16) {
            #pragma unroll
            for (int ni = 0; ni < 8; ni++) {
                int gc = j * 64 + ni * 8 + lm4 * 2;
                if (gc     > grow0) s[ni][0] = -INFINITY;
                if (gc + 1 > grow0) s[ni][1] = -INFINITY;
                if (gc     > grow1) s[ni][2] = -INFINITY;
                if (gc + 1 > grow1) s[ni][3] = -INFINITY;
            }
        }

        // Row max
        float rm0 = -INFINITY, rm1 = -INFINITY;
        #pragma unroll
        for (int ni = 0; ni < 8; ni++) {
            rm0 = fmaxf(rm0, fmaxf(s[ni][0], s[ni][1]));
            rm1 = fmaxf(rm1, fmaxf(s[ni][2], s[ni][3]));
        }
        #pragma unroll
        for (int off = 1; off < 4; off <<= 1) {
            rm0 = fmaxf(rm0, __shfl_xor_sync(0xffffffffu, rm0, off));
            rm1 = fmaxf(rm1, __shfl_xor_sync(0xffffffffu, rm1, off));
        }

        float nm0 = fmaxf(m0, rm0);
        float nm1 = fmaxf(m1, rm1);
        float a0 = ex2f(m0 - nm0);
        float a1 = ex2f(m1 - nm1);
        m0 = nm0; m1 = nm1;

        // Rescale O and l only if some row got a new max
        if (!__all_sync(0xffffffffu, (a0 == 1.0f) && (a1 == 1.0f))) {
            #pragma unroll
            for (int ni = 0; ni < 8; ni++) {
                o[ni][0] *= a0; o[ni][1] *= a0;
                o[ni][2] *= a1; o[ni][3] *= a1;
            }
            lacc[0] *= a0; lacc[1] *= a0;
            lacc[2] *= a1; lacc[3] *= a1;
        }

        // P = 2^(s - m) packed to fp16; O += P@V; l += P@1
        #pragma unroll
        for (int g = 0; g < 4; g++) {
            unsigned ap[4];
            ap[0] = pack_h2(ex2f(s[2*g][0]   - nm0), ex2f(s[2*g][1]   - nm0));
            ap[1] = pack_h2(ex2f(s[2*g][2]   - nm1), ex2f(s[2*g][3]   - nm1));
            ap[2] = pack_h2(ex2f(s[2*g+1][0] - nm0), ex2f(s[2*g+1][1] - nm0));
            ap[3] = pack_h2(ex2f(s[2*g+1][2] - nm1), ex2f(s[2*g+1][3] - nm1));

            unsigned ones2[2] = { ONESH2, ONESH2 };
            mma16(lacc, ap, ones2);

            #pragma unroll
            for (int dg = 0; dg < 4; dg++) {
                unsigned vf[4];
                LDSM4T(vf, voff + g * 16 * RSTR + dg * 32);
                unsigned b0[2] = { vf[0], vf[1] };
                unsigned b1[2] = { vf[2], vf[3] };
                mma16(o[2*dg],     ap, b0);
                mma16(o[2*dg + 1], ap, b1);
            }
        }
    }

    // Epilogue: normalize (l from ones-MMA), convert fp16, store
    float i0 = 1.0f / lacc[0];
    float i1 = 1.0f / lacc[2];
    #pragma unroll
    for (int ni = 0; ni < 8; ni++) {
        int gr = b * SEQ + q0 + w16 + l4;
        int gc = h * HDIM + ni * 8 + lm4 * 2;
        *(unsigned*)&O[(size_t)gr * EMBD + gc] =
            pack_h2(o[ni][0] * i0, o[ni][1] * i0);
        *(unsigned*)&O[(size_t)(gr + 8) * EMBD + gc] =
            pack_h2(o[ni][2] * i1, o[ni][3] * i1);
    }
}

// ---------------------------------------------------------------------------
// Launch
// ---------------------------------------------------------------------------
extern "C" void kernel_launch(void* const* d_in, const int* in_sizes, int n_in,
                              void* d_out, int out_size)
{
    const float* x  = (const float*)d_in[0];
    const float* Wq = (const float*)d_in[1];
    const float* Wk = (const float*)d_in[2];
    const float* Wv = (const float*)d_in[3];
    const float* Wo = (const float*)d_in[4];
    float* out = (float*)d_out;

    __half *Qp, *Kp, *Vp, *Ap, *Xp, *Wp;
    cudaGetSymbolAddress((void**)&Qp, g_Q);
    cudaGetSymbolAddress((void**)&Kp, g_K);
    cudaGetSymbolAddress((void**)&Vp, g_V);
    cudaGetSymbolAddress((void**)&Ap, g_A);
    cudaGetSymbolAddress((void**)&Xp, g_X);
    cudaGetSymbolAddress((void**)&Wp, g_W);

    cudaFuncSetAttribute(gemm_qkv,   cudaFuncAttributeMaxDynamicSharedMemorySize, GSMEM);
    cudaFuncSetAttribute(gemm_out,   cudaFuncAttributeMaxDynamicSharedMemorySize, GSMEM);
    cudaFuncSetAttribute(attn_flash, cudaFuncAttributeMaxDynamicSharedMemorySize, ATTN_SMEM);

    const int XN4 = MROWS * EMBD / 4;
    x2h<<<XN4 / 256, 256>>>((const float4*)x, (uint2*)Xp, XN4);

    dim3 gt(EMBD / 32, EMBD / 32, 4);
    round_wt<<<gt, 256>>>(Wq, Wk, Wv, Wo, Wp);

    dim3 gqkv(EMBD / 128, MROWS / 128, 3);
    gemm_qkv<<<gqkv, 256, GSMEM>>>(Xp, Wp, Qp, Kp, Vp);

    dim3 ga(SEQ / 128, BATCH * NHEAD);
    attn_flash<<<ga, 256, ATTN_SMEM>>>(Qp, Kp, Vp, Ap);

    dim3 go(EMBD / 128, MROWS / 128);
    gemm_out<<<go, 256, GSMEM>>>(Ap, Wp + 3 * (size_t)EMBD * EMBD, out);
}